// round 13
// baseline (speedup 1.0000x reference)
#include <cuda_runtime.h>

#define N_NODES 50000
#define IN_C   128
#define HID_C  128
#define OUT_C  64
#define CAP    128          // neighbor bucket capacity (Poisson mean 16 -> safe)

// ---------------------------------------------------------------------------
// Device-global scratch (no allocations allowed; zero-initialized at load)
// ---------------------------------------------------------------------------
__device__ int   g_cnt [N_NODES];             // per-node neighbor count (self-resetting)
__device__ int   g_adj [N_NODES * CAP];       // bucketed adjacency (src ids)
__device__ float g_mean[N_NODES * IN_C];      // mean of neighbor x
__device__ float g_h   [N_NODES * HID_C];     // layer-1 activations
__device__ float g_t   [N_NODES * OUT_C];     // h @ W2_l

// ---------------------------------------------------------------------------
__global__ void k_fill(const int* __restrict__ ei, int E) {
    int e = blockIdx.x * blockDim.x + threadIdx.x;
    if (e >= E) return;
    int s = ei[e];
    int d = ei[E + e];
    int pos = atomicAdd(&g_cnt[d], 1);
    if (pos < CAP) g_adj[d * CAP + pos] = s;
}

// ---------------------------------------------------------------------------
// Aggregation 1: one warp per node; 512-thread blocks for more resident warps.
// ---------------------------------------------------------------------------
__global__ __launch_bounds__(512) void k_agg1(const float* __restrict__ x) {
    int node = blockIdx.x * (blockDim.x >> 5) + (threadIdx.x >> 5);
    int lane = threadIdx.x & 31;
    if (node >= N_NODES) return;

    int deg = min(g_cnt[node], CAP);
    const int* adj = g_adj + node * CAP;

    float4 a0 = make_float4(0.f, 0.f, 0.f, 0.f);
    float4 a1 = make_float4(0.f, 0.f, 0.f, 0.f);
    float4 a2 = make_float4(0.f, 0.f, 0.f, 0.f);
    float4 a3 = make_float4(0.f, 0.f, 0.f, 0.f);

    int p = 0;
    for (; p + 8 <= deg; p += 8) {
        int4 i0 = *(const int4*)(adj + p);
        int4 i1 = *(const int4*)(adj + p + 4);
        float4 v0 = ((const float4*)(x + (size_t)i0.x * IN_C))[lane];
        float4 v1 = ((const float4*)(x + (size_t)i0.y * IN_C))[lane];
        float4 v2 = ((const float4*)(x + (size_t)i0.z * IN_C))[lane];
        float4 v3 = ((const float4*)(x + (size_t)i0.w * IN_C))[lane];
        float4 v4 = ((const float4*)(x + (size_t)i1.x * IN_C))[lane];
        float4 v5 = ((const float4*)(x + (size_t)i1.y * IN_C))[lane];
        float4 v6 = ((const float4*)(x + (size_t)i1.z * IN_C))[lane];
        float4 v7 = ((const float4*)(x + (size_t)i1.w * IN_C))[lane];
        a0.x += v0.x; a0.y += v0.y; a0.z += v0.z; a0.w += v0.w;
        a1.x += v1.x; a1.y += v1.y; a1.z += v1.z; a1.w += v1.w;
        a2.x += v2.x; a2.y += v2.y; a2.z += v2.z; a2.w += v2.w;
        a3.x += v3.x; a3.y += v3.y; a3.z += v3.z; a3.w += v3.w;
        a0.x += v4.x; a0.y += v4.y; a0.z += v4.z; a0.w += v4.w;
        a1.x += v5.x; a1.y += v5.y; a1.z += v5.z; a1.w += v5.w;
        a2.x += v6.x; a2.y += v6.y; a2.z += v6.z; a2.w += v6.w;
        a3.x += v7.x; a3.y += v7.y; a3.z += v7.z; a3.w += v7.w;
    }
    if (p + 4 <= deg) {
        int4 i0 = *(const int4*)(adj + p);
        float4 v0 = ((const float4*)(x + (size_t)i0.x * IN_C))[lane];
        float4 v1 = ((const float4*)(x + (size_t)i0.y * IN_C))[lane];
        float4 v2 = ((const float4*)(x + (size_t)i0.z * IN_C))[lane];
        float4 v3 = ((const float4*)(x + (size_t)i0.w * IN_C))[lane];
        a0.x += v0.x; a0.y += v0.y; a0.z += v0.z; a0.w += v0.w;
        a1.x += v1.x; a1.y += v1.y; a1.z += v1.z; a1.w += v1.w;
        a2.x += v2.x; a2.y += v2.y; a2.z += v2.z; a2.w += v2.w;
        a3.x += v3.x; a3.y += v3.y; a3.z += v3.z; a3.w += v3.w;
        p += 4;
    }
    for (; p < deg; p++) {
        int s = adj[p];
        float4 v = ((const float4*)(x + (size_t)s * IN_C))[lane];
        a0.x += v.x; a0.y += v.y; a0.z += v.z; a0.w += v.w;
    }
    float4 acc;
    acc.x = (a0.x + a1.x) + (a2.x + a3.x);
    acc.y = (a0.y + a1.y) + (a2.y + a3.y);
    acc.z = (a0.z + a1.z) + (a2.z + a3.z);
    acc.w = (a0.w + a1.w) + (a2.w + a3.w);
    float inv = (deg > 0) ? 1.f / (float)deg : 0.f;
    acc.x *= inv; acc.y *= inv; acc.z *= inv; acc.w *= inv;
    ((float4*)(g_mean + (size_t)node * IN_C))[lane] = acc;
}

// ---------------------------------------------------------------------------
// TF32 / MMA helpers
// ---------------------------------------------------------------------------
__device__ __forceinline__ unsigned f2tf32(float f) {
    unsigned u;
    asm("cvt.rna.tf32.f32 %0, %1;" : "=r"(u) : "f"(f));
    return u;
}

__device__ __forceinline__ void mma_tf32(float d[4], const unsigned a[4],
                                         const unsigned b[2]) {
    asm volatile(
        "mma.sync.aligned.m16n8k8.row.col.f32.tf32.tf32.f32 "
        "{%0,%1,%2,%3}, {%4,%5,%6,%7}, {%8,%9}, {%0,%1,%2,%3};"
        : "+f"(d[0]), "+f"(d[1]), "+f"(d[2]), "+f"(d[3])
        : "r"(a[0]), "r"(a[1]), "r"(a[2]), "r"(a[3]), "r"(b[0]), "r"(b[1]));
}

#define SSTR 136   // smem row stride in words: 136 mod 32 = 8 -> conflict-free

// ---------------------------------------------------------------------------
// GEMM 1 (TF32, k-major smem — exact R8 config, the measured optimum):
//   h = relu( [mean | x] @ [W1_l ; W1_r] + b1 )   (N=128, K=256)
// Block 128x128, BK=16, double-buffered, 8 warps 2x4, warp tile 64x32.
// ---------------------------------------------------------------------------
__global__ __launch_bounds__(256) void k_gemm1(const float* __restrict__ x,
                                               const float* __restrict__ W1l,
                                               const float* __restrict__ b1,
                                               const float* __restrict__ W1r) {
    __shared__ unsigned As[2][16][SSTR];   // [buf][k][m]
    __shared__ unsigned Bs[2][16][SSTR];   // [buf][k][n]

    const int tid  = threadIdx.x;
    const int brow = blockIdx.x * 128;

    const int am  = tid & 127;
    const int akb = (tid >> 7) * 8;
    const int ra  = min(brow + am, N_NODES - 1);
    const int bkr = tid >> 4;
    const int bnc = (tid & 15) * 8;

    const int wid  = tid >> 5;
    const int lane = tid & 31;
    const int g    = lane >> 2;
    const int t    = lane & 3;
    const int m0   = (wid >> 2) * 64;
    const int n0   = (wid & 3) * 32;

    float acc[4][4][4];
#pragma unroll
    for (int mt = 0; mt < 4; mt++)
#pragma unroll
        for (int nt = 0; nt < 4; nt++)
#pragma unroll
            for (int r = 0; r < 4; r++) acc[mt][nt][r] = 0.f;

    float4 pa0, pa1, pb0, pb1;

    auto loadG = [&](int kc) {
        int kg = kc + akb;
        const float* srcA = (kg < 128) ? (g_mean + (size_t)ra * 128 + kg)
                                       : (x + (size_t)ra * 128 + (kg - 128));
        pa0 = *(const float4*)(srcA);
        pa1 = *(const float4*)(srcA + 4);
        int kgb = kc + bkr;
        const float* srcB = (kgb < 128) ? (W1l + (size_t)kgb * 128 + bnc)
                                        : (W1r + (size_t)(kgb - 128) * 128 + bnc);
        pb0 = *(const float4*)(srcB);
        pb1 = *(const float4*)(srcB + 4);
    };
    auto storeS = [&](int buf) {
        As[buf][akb + 0][am] = f2tf32(pa0.x);
        As[buf][akb + 1][am] = f2tf32(pa0.y);
        As[buf][akb + 2][am] = f2tf32(pa0.z);
        As[buf][akb + 3][am] = f2tf32(pa0.w);
        As[buf][akb + 4][am] = f2tf32(pa1.x);
        As[buf][akb + 5][am] = f2tf32(pa1.y);
        As[buf][akb + 6][am] = f2tf32(pa1.z);
        As[buf][akb + 7][am] = f2tf32(pa1.w);
        uint4 u0 = make_uint4(f2tf32(pb0.x), f2tf32(pb0.y), f2tf32(pb0.z), f2tf32(pb0.w));
        uint4 u1 = make_uint4(f2tf32(pb1.x), f2tf32(pb1.y), f2tf32(pb1.z), f2tf32(pb1.w));
        *(uint4*)&Bs[buf][bkr][bnc]     = u0;
        *(uint4*)&Bs[buf][bkr][bnc + 4] = u1;
    };

    loadG(0);
    storeS(0);
    __syncthreads();

    int buf = 0;
    for (int kc = 0; kc < 256; kc += 16) {
        bool has_next = (kc + 16) < 256;
        if (has_next) loadG(kc + 16);

#pragma unroll
        for (int kk = 0; kk < 16; kk += 8) {
            unsigned afr[4][4];
#pragma unroll
            for (int mt = 0; mt < 4; mt++) {
                int mr = m0 + mt * 16 + g;
                afr[mt][0] = As[buf][kk + t][mr];
                afr[mt][1] = As[buf][kk + t][mr + 8];
                afr[mt][2] = As[buf][kk + t + 4][mr];
                afr[mt][3] = As[buf][kk + t + 4][mr + 8];
            }
            unsigned bfr[4][2];
#pragma unroll
            for (int nt = 0; nt < 4; nt++) {
                int nr = n0 + nt * 8 + g;
                bfr[nt][0] = Bs[buf][kk + t][nr];
                bfr[nt][1] = Bs[buf][kk + t + 4][nr];
            }
#pragma unroll
            for (int mt = 0; mt < 4; mt++)
#pragma unroll
                for (int nt = 0; nt < 4; nt++)
                    mma_tf32(acc[mt][nt], afr[mt], bfr[nt]);
        }

        if (has_next) {
            storeS(buf ^ 1);
            __syncthreads();
            buf ^= 1;
        }
    }

#pragma unroll
    for (int nt = 0; nt < 4; nt++) {
        int c = n0 + nt * 8 + 2 * t;
        float2 bb = *(const float2*)(b1 + c);
#pragma unroll
        for (int mt = 0; mt < 4; mt++) {
            int r0 = brow + m0 + mt * 16 + g;
            if (r0 < N_NODES) {
                float2 o;
                o.x = fmaxf(acc[mt][nt][0] + bb.x, 0.f);
                o.y = fmaxf(acc[mt][nt][1] + bb.y, 0.f);
                *(float2*)(g_h + (size_t)r0 * 128 + c) = o;
            }
            int r1 = r0 + 8;
            if (r1 < N_NODES) {
                float2 o;
                o.x = fmaxf(acc[mt][nt][2] + bb.x, 0.f);
                o.y = fmaxf(acc[mt][nt][3] + bb.y, 0.f);
                *(float2*)(g_h + (size_t)r1 * 128 + c) = o;
            }
        }
    }
}

// ---------------------------------------------------------------------------
// GEMM 2 (TF32, k-major smem — exact R8 config):
//   t = h @ W2_l ; out = h @ W2_r + b2   (N = 64+64, K = 128)
// ---------------------------------------------------------------------------
__global__ __launch_bounds__(256) void k_gemm2(const float* __restrict__ W2l,
                                               const float* __restrict__ b2,
                                               const float* __restrict__ W2r,
                                               float* __restrict__ out) {
    __shared__ unsigned As[2][16][SSTR];
    __shared__ unsigned Bs[2][16][SSTR];

    const int tid  = threadIdx.x;
    const int brow = blockIdx.x * 128;

    const int am  = tid & 127;
    const int akb = (tid >> 7) * 8;
    const int ra  = min(brow + am, N_NODES - 1);
    const int bkr = tid >> 4;
    const int bnc = (tid & 15) * 8;

    const int wid  = tid >> 5;
    const int lane = tid & 31;
    const int g    = lane >> 2;
    const int t    = lane & 3;
    const int m0   = (wid >> 2) * 64;
    const int n0   = (wid & 3) * 32;

    float acc[4][4][4];
#pragma unroll
    for (int mt = 0; mt < 4; mt++)
#pragma unroll
        for (int nt = 0; nt < 4; nt++)
#pragma unroll
            for (int r = 0; r < 4; r++) acc[mt][nt][r] = 0.f;

    float4 pa0, pa1, pb0, pb1;

    auto loadG = [&](int kc) {
        const float* srcA = g_h + (size_t)ra * 128 + kc + akb;
        pa0 = *(const float4*)(srcA);
        pa1 = *(const float4*)(srcA + 4);
        int kg = kc + bkr;
        const float* srcB = (bnc < 64) ? (W2l + (size_t)kg * 64 + bnc)
                                       : (W2r + (size_t)kg * 64 + (bnc - 64));
        pb0 = *(const float4*)(srcB);
        pb1 = *(const float4*)(srcB + 4);
    };
    auto storeS = [&](int buf) {
        As[buf][akb + 0][am] = f2tf32(pa0.x);
        As[buf][akb + 1][am] = f2tf32(pa0.y);
        As[buf][akb + 2][am] = f2tf32(pa0.z);
        As[buf][akb + 3][am] = f2tf32(pa0.w);
        As[buf][akb + 4][am] = f2tf32(pa1.x);
        As[buf][akb + 5][am] = f2tf32(pa1.y);
        As[buf][akb + 6][am] = f2tf32(pa1.z);
        As[buf][akb + 7][am] = f2tf32(pa1.w);
        uint4 u0 = make_uint4(f2tf32(pb0.x), f2tf32(pb0.y), f2tf32(pb0.z), f2tf32(pb0.w));
        uint4 u1 = make_uint4(f2tf32(pb1.x), f2tf32(pb1.y), f2tf32(pb1.z), f2tf32(pb1.w));
        *(uint4*)&Bs[buf][bkr][bnc]     = u0;
        *(uint4*)&Bs[buf][bkr][bnc + 4] = u1;
    };

    loadG(0);
    storeS(0);
    __syncthreads();

    int buf = 0;
    for (int kc = 0; kc < 128; kc += 16) {
        bool has_next = (kc + 16) < 128;
        if (has_next) loadG(kc + 16);

#pragma unroll
        for (int kk = 0; kk < 16; kk += 8) {
            unsigned afr[4][4];
#pragma unroll
            for (int mt = 0; mt < 4; mt++) {
                int mr = m0 + mt * 16 + g;
                afr[mt][0] = As[buf][kk + t][mr];
                afr[mt][1] = As[buf][kk + t][mr + 8];
                afr[mt][2] = As[buf][kk + t + 4][mr];
                afr[mt][3] = As[buf][kk + t + 4][mr + 8];
            }
            unsigned bfr[4][2];
#pragma unroll
            for (int nt = 0; nt < 4; nt++) {
                int nr = n0 + nt * 8 + g;
                bfr[nt][0] = Bs[buf][kk + t][nr];
                bfr[nt][1] = Bs[buf][kk + t + 4][nr];
            }
#pragma unroll
            for (int mt = 0; mt < 4; mt++)
#pragma unroll
                for (int nt = 0; nt < 4; nt++)
                    mma_tf32(acc[mt][nt], afr[mt], bfr[nt]);
        }

        if (has_next) {
            storeS(buf ^ 1);
            __syncthreads();
            buf ^= 1;
        }
    }

#pragma unroll
    for (int nt = 0; nt < 4; nt++) {
        int c = n0 + nt * 8 + 2 * t;
        if (c < 64) {
#pragma unroll
            for (int mt = 0; mt < 4; mt++) {
                int r0 = brow + m0 + mt * 16 + g;
                if (r0 < N_NODES)
                    *(float2*)(g_t + (size_t)r0 * 64 + c) =
                        make_float2(acc[mt][nt][0], acc[mt][nt][1]);
                int r1 = r0 + 8;
                if (r1 < N_NODES)
                    *(float2*)(g_t + (size_t)r1 * 64 + c) =
                        make_float2(acc[mt][nt][2], acc[mt][nt][3]);
            }
        } else {
            int co = c - 64;
            float2 bb = *(const float2*)(b2 + co);
#pragma unroll
            for (int mt = 0; mt < 4; mt++) {
                int r0 = brow + m0 + mt * 16 + g;
                if (r0 < N_NODES)
                    *(float2*)(out + (size_t)r0 * 64 + co) =
                        make_float2(acc[mt][nt][0] + bb.x, acc[mt][nt][1] + bb.y);
                int r1 = r0 + 8;
                if (r1 < N_NODES)
                    *(float2*)(out + (size_t)r1 * 64 + co) =
                        make_float2(acc[mt][nt][2] + bb.x, acc[mt][nt][3] + bb.y);
            }
        }
    }
}

// ---------------------------------------------------------------------------
// Aggregation 2 + final; resets g_cnt for the next launch (replaces k_zero).
// 512-thread blocks.
// ---------------------------------------------------------------------------
__global__ __launch_bounds__(512) void k_agg2(float* __restrict__ out) {
    int node = blockIdx.x * (blockDim.x >> 5) + (threadIdx.x >> 5);
    int lane = threadIdx.x & 31;
    if (node >= N_NODES) return;

    int deg = min(g_cnt[node], CAP);
    if (lane == 0) g_cnt[node] = 0;    // reset for next launch
    const int* adj = g_adj + node * CAP;

    float2 a0 = make_float2(0.f, 0.f);
    float2 a1 = make_float2(0.f, 0.f);
    float2 a2 = make_float2(0.f, 0.f);
    float2 a3 = make_float2(0.f, 0.f);

    int p = 0;
    for (; p + 8 <= deg; p += 8) {
        int4 i0 = *(const int4*)(adj + p);
        int4 i1 = *(const int4*)(adj + p + 4);
        float2 v0 = ((const float2*)(g_t + (size_t)i0.x * OUT_C))[lane];
        float2 v1 = ((const float2*)(g_t + (size_t)i0.y * OUT_C))[lane];
        float2 v2 = ((const float2*)(g_t + (size_t)i0.z * OUT_C))[lane];
        float2 v3 = ((const float2*)(g_t + (size_t)i0.w * OUT_C))[lane];
        float2 v4 = ((const float2*)(g_t + (size_t)i1.x * OUT_C))[lane];
        float2 v5 = ((const float2*)(g_t + (size_t)i1.y * OUT_C))[lane];
        float2 v6 = ((const float2*)(g_t + (size_t)i1.z * OUT_C))[lane];
        float2 v7 = ((const float2*)(g_t + (size_t)i1.w * OUT_C))[lane];
        a0.x += v0.x; a0.y += v0.y;
        a1.x += v1.x; a1.y += v1.y;
        a2.x += v2.x; a2.y += v2.y;
        a3.x += v3.x; a3.y += v3.y;
        a0.x += v4.x; a0.y += v4.y;
        a1.x += v5.x; a1.y += v5.y;
        a2.x += v6.x; a2.y += v6.y;
        a3.x += v7.x; a3.y += v7.y;
    }
    if (p + 4 <= deg) {
        int4 i0 = *(const int4*)(adj + p);
        float2 v0 = ((const float2*)(g_t + (size_t)i0.x * OUT_C))[lane];
        float2 v1 = ((const float2*)(g_t + (size_t)i0.y * OUT_C))[lane];
        float2 v2 = ((const float2*)(g_t + (size_t)i0.z * OUT_C))[lane];
        float2 v3 = ((const float2*)(g_t + (size_t)i0.w * OUT_C))[lane];
        a0.x += v0.x; a0.y += v0.y;
        a1.x += v1.x; a1.y += v1.y;
        a2.x += v2.x; a2.y += v2.y;
        a3.x += v3.x; a3.y += v3.y;
        p += 4;
    }
    for (; p < deg; p++) {
        int s = adj[p];
        float2 v = ((const float2*)(g_t + (size_t)s * OUT_C))[lane];
        a0.x += v.x; a0.y += v.y;
    }
    float inv = (deg > 0) ? 1.f / (float)deg : 0.f;
    float sx = ((a0.x + a1.x) + (a2.x + a3.x)) * inv;
    float sy = ((a0.y + a1.y) + (a2.y + a3.y)) * inv;

    float2* o = (float2*)(out + (size_t)node * OUT_C) + lane;
    float2 cur = *o;
    cur.x += sx;
    cur.y += sy;
    *o = cur;
}

// ---------------------------------------------------------------------------
extern "C" void kernel_launch(void* const* d_in, const int* in_sizes, int n_in,
                              void* d_out, int out_size) {
    const float* x   = (const float*)d_in[0];
    const int*   ei  = (const int*)d_in[1];     // int32 (JAX default x64 off)
    const float* W1l = (const float*)d_in[2];
    const float* b1  = (const float*)d_in[3];
    const float* W1r = (const float*)d_in[4];
    const float* W2l = (const float*)d_in[5];
    const float* b2  = (const float*)d_in[6];
    const float* W2r = (const float*)d_in[7];
    float* out = (float*)d_out;

    const int E = in_sizes[1] / 2;

    k_fill<<<(E + 255) / 256, 256>>>(ei, E);

    k_agg1<<<(N_NODES + 15) / 16, 512>>>(x);
    k_gemm1<<<(N_NODES + 127) / 128, 256>>>(x, W1l, b1, W1r);

    k_gemm2<<<(N_NODES + 127) / 128, 256>>>(W2l, b2, W2r, out);
    k_agg2<<<(N_NODES + 15) / 16, 512>>>(out);
}

// round 14
// speedup vs baseline: 1.6128x; 1.6128x over previous
#include <cuda_runtime.h>

#define N_NODES 50000
#define IN_C   128
#define HID_C  128
#define OUT_C  64
#define CAP    128          // neighbor bucket capacity (Poisson mean 16 -> safe)

// ---------------------------------------------------------------------------
// Device-global scratch (no allocations allowed)
// ---------------------------------------------------------------------------
__device__ int   g_cnt [N_NODES];             // per-node neighbor count
__device__ int   g_adj [N_NODES * CAP];       // bucketed adjacency (src ids)
__device__ float g_mean[N_NODES * IN_C];      // mean of neighbor x
__device__ float g_h   [N_NODES * HID_C];     // layer-1 activations
__device__ float g_t   [N_NODES * OUT_C];     // h @ W2_l

// ---------------------------------------------------------------------------
__global__ void k_zero() {
    int i = blockIdx.x * blockDim.x + threadIdx.x;
    if (i < N_NODES) g_cnt[i] = 0;
}

__global__ void k_fill(const int* __restrict__ ei, int E) {
    int e = blockIdx.x * blockDim.x + threadIdx.x;
    if (e >= E) return;
    int s = ei[e];
    int d = ei[E + e];
    int pos = atomicAdd(&g_cnt[d], 1);
    if (pos < CAP) g_adj[d * CAP + pos] = s;
}

// ---------------------------------------------------------------------------
// Aggregation 1: one warp per node, lane owns one float4; unroll-8.
// ---------------------------------------------------------------------------
__global__ void k_agg1(const float* __restrict__ x) {
    int node = blockIdx.x * (blockDim.x >> 5) + (threadIdx.x >> 5);
    int lane = threadIdx.x & 31;
    if (node >= N_NODES) return;

    int deg = min(g_cnt[node], CAP);
    const int* adj = g_adj + node * CAP;

    float4 a0 = make_float4(0.f, 0.f, 0.f, 0.f);
    float4 a1 = make_float4(0.f, 0.f, 0.f, 0.f);
    float4 a2 = make_float4(0.f, 0.f, 0.f, 0.f);
    float4 a3 = make_float4(0.f, 0.f, 0.f, 0.f);

    int p = 0;
    for (; p + 8 <= deg; p += 8) {
        int4 i0 = *(const int4*)(adj + p);
        int4 i1 = *(const int4*)(adj + p + 4);
        float4 v0 = ((const float4*)(x + (size_t)i0.x * IN_C))[lane];
        float4 v1 = ((const float4*)(x + (size_t)i0.y * IN_C))[lane];
        float4 v2 = ((const float4*)(x + (size_t)i0.z * IN_C))[lane];
        float4 v3 = ((const float4*)(x + (size_t)i0.w * IN_C))[lane];
        float4 v4 = ((const float4*)(x + (size_t)i1.x * IN_C))[lane];
        float4 v5 = ((const float4*)(x + (size_t)i1.y * IN_C))[lane];
        float4 v6 = ((const float4*)(x + (size_t)i1.z * IN_C))[lane];
        float4 v7 = ((const float4*)(x + (size_t)i1.w * IN_C))[lane];
        a0.x += v0.x; a0.y += v0.y; a0.z += v0.z; a0.w += v0.w;
        a1.x += v1.x; a1.y += v1.y; a1.z += v1.z; a1.w += v1.w;
        a2.x += v2.x; a2.y += v2.y; a2.z += v2.z; a2.w += v2.w;
        a3.x += v3.x; a3.y += v3.y; a3.z += v3.z; a3.w += v3.w;
        a0.x += v4.x; a0.y += v4.y; a0.z += v4.z; a0.w += v4.w;
        a1.x += v5.x; a1.y += v5.y; a1.z += v5.z; a1.w += v5.w;
        a2.x += v6.x; a2.y += v6.y; a2.z += v6.z; a2.w += v6.w;
        a3.x += v7.x; a3.y += v7.y; a3.z += v7.z; a3.w += v7.w;
    }
    if (p + 4 <= deg) {
        int4 i0 = *(const int4*)(adj + p);
        float4 v0 = ((const float4*)(x + (size_t)i0.x * IN_C))[lane];
        float4 v1 = ((const float4*)(x + (size_t)i0.y * IN_C))[lane];
        float4 v2 = ((const float4*)(x + (size_t)i0.z * IN_C))[lane];
        float4 v3 = ((const float4*)(x + (size_t)i0.w * IN_C))[lane];
        a0.x += v0.x; a0.y += v0.y; a0.z += v0.z; a0.w += v0.w;
        a1.x += v1.x; a1.y += v1.y; a1.z += v1.z; a1.w += v1.w;
        a2.x += v2.x; a2.y += v2.y; a2.z += v2.z; a2.w += v2.w;
        a3.x += v3.x; a3.y += v3.y; a3.z += v3.z; a3.w += v3.w;
        p += 4;
    }
    for (; p < deg; p++) {
        int s = adj[p];
        float4 v = ((const float4*)(x + (size_t)s * IN_C))[lane];
        a0.x += v.x; a0.y += v.y; a0.z += v.z; a0.w += v.w;
    }
    float4 acc;
    acc.x = (a0.x + a1.x) + (a2.x + a3.x);
    acc.y = (a0.y + a1.y) + (a2.y + a3.y);
    acc.z = (a0.z + a1.z) + (a2.z + a3.z);
    acc.w = (a0.w + a1.w) + (a2.w + a3.w);
    float inv = (deg > 0) ? 1.f / (float)deg : 0.f;
    acc.x *= inv; acc.y *= inv; acc.z *= inv; acc.w *= inv;
    ((float4*)(g_mean + (size_t)node * IN_C))[lane] = acc;
}

// ---------------------------------------------------------------------------
// TF32 / MMA helpers
// ---------------------------------------------------------------------------
__device__ __forceinline__ unsigned f2tf32(float f) {
    unsigned u;
    asm("cvt.rna.tf32.f32 %0, %1;" : "=r"(u) : "f"(f));
    return u;
}

__device__ __forceinline__ void mma_tf32(float d[4], const unsigned a[4],
                                         const unsigned b[2]) {
    asm volatile(
        "mma.sync.aligned.m16n8k8.row.col.f32.tf32.tf32.f32 "
        "{%0,%1,%2,%3}, {%4,%5,%6,%7}, {%8,%9}, {%0,%1,%2,%3};"
        : "+f"(d[0]), "+f"(d[1]), "+f"(d[2]), "+f"(d[3])
        : "r"(a[0]), "r"(a[1]), "r"(a[2]), "r"(a[3]), "r"(b[0]), "r"(b[1]));
}

#define SSTR 136   // smem row stride in words: 136 mod 32 = 8 -> conflict-free

// ---------------------------------------------------------------------------
// GEMM 1 (TF32, k-major smem): h = relu( [mean | x] @ [W1_l ; W1_r] + b1 )
// Block 128x128, BK=16, double-buffered, 8 warps 2x4, warp tile 64x32.
// ---------------------------------------------------------------------------
__global__ __launch_bounds__(256) void k_gemm1(const float* __restrict__ x,
                                               const float* __restrict__ W1l,
                                               const float* __restrict__ b1,
                                               const float* __restrict__ W1r) {
    __shared__ unsigned As[2][16][SSTR];   // [buf][k][m]
    __shared__ unsigned Bs[2][16][SSTR];   // [buf][k][n]

    const int tid  = threadIdx.x;
    const int brow = blockIdx.x * 128;

    const int am  = tid & 127;
    const int akb = (tid >> 7) * 8;
    const int ra  = min(brow + am, N_NODES - 1);
    const int bkr = tid >> 4;
    const int bnc = (tid & 15) * 8;

    const int wid  = tid >> 5;
    const int lane = tid & 31;
    const int g    = lane >> 2;
    const int t    = lane & 3;
    const int m0   = (wid >> 2) * 64;
    const int n0   = (wid & 3) * 32;

    float acc[4][4][4];
#pragma unroll
    for (int mt = 0; mt < 4; mt++)
#pragma unroll
        for (int nt = 0; nt < 4; nt++)
#pragma unroll
            for (int r = 0; r < 4; r++) acc[mt][nt][r] = 0.f;

    float4 pa0, pa1, pb0, pb1;

    auto loadG = [&](int kc) {
        int kg = kc + akb;
        const float* srcA = (kg < 128) ? (g_mean + (size_t)ra * 128 + kg)
                                       : (x + (size_t)ra * 128 + (kg - 128));
        pa0 = *(const float4*)(srcA);
        pa1 = *(const float4*)(srcA + 4);
        int kgb = kc + bkr;
        const float* srcB = (kgb < 128) ? (W1l + (size_t)kgb * 128 + bnc)
                                        : (W1r + (size_t)(kgb - 128) * 128 + bnc);
        pb0 = *(const float4*)(srcB);
        pb1 = *(const float4*)(srcB + 4);
    };
    auto storeS = [&](int buf) {
        As[buf][akb + 0][am] = f2tf32(pa0.x);
        As[buf][akb + 1][am] = f2tf32(pa0.y);
        As[buf][akb + 2][am] = f2tf32(pa0.z);
        As[buf][akb + 3][am] = f2tf32(pa0.w);
        As[buf][akb + 4][am] = f2tf32(pa1.x);
        As[buf][akb + 5][am] = f2tf32(pa1.y);
        As[buf][akb + 6][am] = f2tf32(pa1.z);
        As[buf][akb + 7][am] = f2tf32(pa1.w);
        uint4 u0 = make_uint4(f2tf32(pb0.x), f2tf32(pb0.y), f2tf32(pb0.z), f2tf32(pb0.w));
        uint4 u1 = make_uint4(f2tf32(pb1.x), f2tf32(pb1.y), f2tf32(pb1.z), f2tf32(pb1.w));
        *(uint4*)&Bs[buf][bkr][bnc]     = u0;
        *(uint4*)&Bs[buf][bkr][bnc + 4] = u1;
    };

    loadG(0);
    storeS(0);
    __syncthreads();

    int buf = 0;
    for (int kc = 0; kc < 256; kc += 16) {
        bool has_next = (kc + 16) < 256;
        if (has_next) loadG(kc + 16);

#pragma unroll
        for (int kk = 0; kk < 16; kk += 8) {
            unsigned afr[4][4];
#pragma unroll
            for (int mt = 0; mt < 4; mt++) {
                int mr = m0 + mt * 16 + g;
                afr[mt][0] = As[buf][kk + t][mr];
                afr[mt][1] = As[buf][kk + t][mr + 8];
                afr[mt][2] = As[buf][kk + t + 4][mr];
                afr[mt][3] = As[buf][kk + t + 4][mr + 8];
            }
            unsigned bfr[4][2];
#pragma unroll
            for (int nt = 0; nt < 4; nt++) {
                int nr = n0 + nt * 8 + g;
                bfr[nt][0] = Bs[buf][kk + t][nr];
                bfr[nt][1] = Bs[buf][kk + t + 4][nr];
            }
#pragma unroll
            for (int mt = 0; mt < 4; mt++)
#pragma unroll
                for (int nt = 0; nt < 4; nt++)
                    mma_tf32(acc[mt][nt], afr[mt], bfr[nt]);
        }

        if (has_next) {
            storeS(buf ^ 1);
            __syncthreads();
            buf ^= 1;
        }
    }

#pragma unroll
    for (int nt = 0; nt < 4; nt++) {
        int c = n0 + nt * 8 + 2 * t;
        float2 bb = *(const float2*)(b1 + c);
#pragma unroll
        for (int mt = 0; mt < 4; mt++) {
            int r0 = brow + m0 + mt * 16 + g;
            if (r0 < N_NODES) {
                float2 o;
                o.x = fmaxf(acc[mt][nt][0] + bb.x, 0.f);
                o.y = fmaxf(acc[mt][nt][1] + bb.y, 0.f);
                *(float2*)(g_h + (size_t)r0 * 128 + c) = o;
            }
            int r1 = r0 + 8;
            if (r1 < N_NODES) {
                float2 o;
                o.x = fmaxf(acc[mt][nt][2] + bb.x, 0.f);
                o.y = fmaxf(acc[mt][nt][3] + bb.y, 0.f);
                *(float2*)(g_h + (size_t)r1 * 128 + c) = o;
            }
        }
    }
}

// ---------------------------------------------------------------------------
// GEMM 2 (TF32, k-major smem): t = h @ W2_l ; out = h @ W2_r + b2
// ---------------------------------------------------------------------------
__global__ __launch_bounds__(256) void k_gemm2(const float* __restrict__ W2l,
                                               const float* __restrict__ b2,
                                               const float* __restrict__ W2r,
                                               float* __restrict__ out) {
    __shared__ unsigned As[2][16][SSTR];
    __shared__ unsigned Bs[2][16][SSTR];

    const int tid  = threadIdx.x;
    const int brow = blockIdx.x * 128;

    const int am  = tid & 127;
    const int akb = (tid >> 7) * 8;
    const int ra  = min(brow + am, N_NODES - 1);
    const int bkr = tid >> 4;
    const int bnc = (tid & 15) * 8;

    const int wid  = tid >> 5;
    const int lane = tid & 31;
    const int g    = lane >> 2;
    const int t    = lane & 3;
    const int m0   = (wid >> 2) * 64;
    const int n0   = (wid & 3) * 32;

    float acc[4][4][4];
#pragma unroll
    for (int mt = 0; mt < 4; mt++)
#pragma unroll
        for (int nt = 0; nt < 4; nt++)
#pragma unroll
            for (int r = 0; r < 4; r++) acc[mt][nt][r] = 0.f;

    float4 pa0, pa1, pb0, pb1;

    auto loadG = [&](int kc) {
        const float* srcA = g_h + (size_t)ra * 128 + kc + akb;
        pa0 = *(const float4*)(srcA);
        pa1 = *(const float4*)(srcA + 4);
        int kg = kc + bkr;
        const float* srcB = (bnc < 64) ? (W2l + (size_t)kg * 64 + bnc)
                                       : (W2r + (size_t)kg * 64 + (bnc - 64));
        pb0 = *(const float4*)(srcB);
        pb1 = *(const float4*)(srcB + 4);
    };
    auto storeS = [&](int buf) {
        As[buf][akb + 0][am] = f2tf32(pa0.x);
        As[buf][akb + 1][am] = f2tf32(pa0.y);
        As[buf][akb + 2][am] = f2tf32(pa0.z);
        As[buf][akb + 3][am] = f2tf32(pa0.w);
        As[buf][akb + 4][am] = f2tf32(pa1.x);
        As[buf][akb + 5][am] = f2tf32(pa1.y);
        As[buf][akb + 6][am] = f2tf32(pa1.z);
        As[buf][akb + 7][am] = f2tf32(pa1.w);
        uint4 u0 = make_uint4(f2tf32(pb0.x), f2tf32(pb0.y), f2tf32(pb0.z), f2tf32(pb0.w));
        uint4 u1 = make_uint4(f2tf32(pb1.x), f2tf32(pb1.y), f2tf32(pb1.z), f2tf32(pb1.w));
        *(uint4*)&Bs[buf][bkr][bnc]     = u0;
        *(uint4*)&Bs[buf][bkr][bnc + 4] = u1;
    };

    loadG(0);
    storeS(0);
    __syncthreads();

    int buf = 0;
    for (int kc = 0; kc < 128; kc += 16) {
        bool has_next = (kc + 16) < 128;
        if (has_next) loadG(kc + 16);

#pragma unroll
        for (int kk = 0; kk < 16; kk += 8) {
            unsigned afr[4][4];
#pragma unroll
            for (int mt = 0; mt < 4; mt++) {
                int mr = m0 + mt * 16 + g;
                afr[mt][0] = As[buf][kk + t][mr];
                afr[mt][1] = As[buf][kk + t][mr + 8];
                afr[mt][2] = As[buf][kk + t + 4][mr];
                afr[mt][3] = As[buf][kk + t + 4][mr + 8];
            }
            unsigned bfr[4][2];
#pragma unroll
            for (int nt = 0; nt < 4; nt++) {
                int nr = n0 + nt * 8 + g;
                bfr[nt][0] = Bs[buf][kk + t][nr];
                bfr[nt][1] = Bs[buf][kk + t + 4][nr];
            }
#pragma unroll
            for (int mt = 0; mt < 4; mt++)
#pragma unroll
                for (int nt = 0; nt < 4; nt++)
                    mma_tf32(acc[mt][nt], afr[mt], bfr[nt]);
        }

        if (has_next) {
            storeS(buf ^ 1);
            __syncthreads();
            buf ^= 1;
        }
    }

#pragma unroll
    for (int nt = 0; nt < 4; nt++) {
        int c = n0 + nt * 8 + 2 * t;
        if (c < 64) {
#pragma unroll
            for (int mt = 0; mt < 4; mt++) {
                int r0 = brow + m0 + mt * 16 + g;
                if (r0 < N_NODES)
                    *(float2*)(g_t + (size_t)r0 * 64 + c) =
                        make_float2(acc[mt][nt][0], acc[mt][nt][1]);
                int r1 = r0 + 8;
                if (r1 < N_NODES)
                    *(float2*)(g_t + (size_t)r1 * 64 + c) =
                        make_float2(acc[mt][nt][2], acc[mt][nt][3]);
            }
        } else {
            int co = c - 64;
            float2 bb = *(const float2*)(b2 + co);
#pragma unroll
            for (int mt = 0; mt < 4; mt++) {
                int r0 = brow + m0 + mt * 16 + g;
                if (r0 < N_NODES)
                    *(float2*)(out + (size_t)r0 * 64 + co) =
                        make_float2(acc[mt][nt][0] + bb.x, acc[mt][nt][1] + bb.y);
                int r1 = r0 + 8;
                if (r1 < N_NODES)
                    *(float2*)(out + (size_t)r1 * 64 + co) =
                        make_float2(acc[mt][nt][2] + bb.x, acc[mt][nt][3] + bb.y);
            }
        }
    }
}

// ---------------------------------------------------------------------------
// Aggregation 2 + final: out[n] += mean_{s in N(n)} t[s] (64 f32/node)
// ---------------------------------------------------------------------------
__global__ void k_agg2(float* __restrict__ out) {
    int node = blockIdx.x * (blockDim.x >> 5) + (threadIdx.x >> 5);
    int lane = threadIdx.x & 31;
    if (node >= N_NODES) return;

    int deg = min(g_cnt[node], CAP);
    const int* adj = g_adj + node * CAP;

    float2 a0 = make_float2(0.f, 0.f);
    float2 a1 = make_float2(0.f, 0.f);
    float2 a2 = make_float2(0.f, 0.f);
    float2 a3 = make_float2(0.f, 0.f);

    int p = 0;
    for (; p + 8 <= deg; p += 8) {
        int4 i0 = *(const int4*)(adj + p);
        int4 i1 = *(const int4*)(adj + p + 4);
        float2 v0 = ((const float2*)(g_t + (size_t)i0.x * OUT_C))[lane];
        float2 v1 = ((const float2*)(g_t + (size_t)i0.y * OUT_C))[lane];
        float2 v2 = ((const float2*)(g_t + (size_t)i0.z * OUT_C))[lane];
        float2 v3 = ((const float2*)(g_t + (size_t)i0.w * OUT_C))[lane];
        float2 v4 = ((const float2*)(g_t + (size_t)i1.x * OUT_C))[lane];
        float2 v5 = ((const float2*)(g_t + (size_t)i1.y * OUT_C))[lane];
        float2 v6 = ((const float2*)(g_t + (size_t)i1.z * OUT_C))[lane];
        float2 v7 = ((const float2*)(g_t + (size_t)i1.w * OUT_C))[lane];
        a0.x += v0.x; a0.y += v0.y;
        a1.x += v1.x; a1.y += v1.y;
        a2.x += v2.x; a2.y += v2.y;
        a3.x += v3.x; a3.y += v3.y;
        a0.x += v4.x; a0.y += v4.y;
        a1.x += v5.x; a1.y += v5.y;
        a2.x += v6.x; a2.y += v6.y;
        a3.x += v7.x; a3.y += v7.y;
    }
    if (p + 4 <= deg) {
        int4 i0 = *(const int4*)(adj + p);
        float2 v0 = ((const float2*)(g_t + (size_t)i0.x * OUT_C))[lane];
        float2 v1 = ((const float2*)(g_t + (size_t)i0.y * OUT_C))[lane];
        float2 v2 = ((const float2*)(g_t + (size_t)i0.z * OUT_C))[lane];
        float2 v3 = ((const float2*)(g_t + (size_t)i0.w * OUT_C))[lane];
        a0.x += v0.x; a0.y += v0.y;
        a1.x += v1.x; a1.y += v1.y;
        a2.x += v2.x; a2.y += v2.y;
        a3.x += v3.x; a3.y += v3.y;
        p += 4;
    }
    for (; p < deg; p++) {
        int s = adj[p];
        float2 v = ((const float2*)(g_t + (size_t)s * OUT_C))[lane];
        a0.x += v.x; a0.y += v.y;
    }
    float inv = (deg > 0) ? 1.f / (float)deg : 0.f;
    float sx = ((a0.x + a1.x) + (a2.x + a3.x)) * inv;
    float sy = ((a0.y + a1.y) + (a2.y + a3.y)) * inv;

    float2* o = (float2*)(out + (size_t)node * OUT_C) + lane;
    float2 cur = *o;
    cur.x += sx;
    cur.y += sy;
    *o = cur;
}

// ---------------------------------------------------------------------------
extern "C" void kernel_launch(void* const* d_in, const int* in_sizes, int n_in,
                              void* d_out, int out_size) {
    const float* x   = (const float*)d_in[0];
    const int*   ei  = (const int*)d_in[1];     // int32 (JAX default x64 off)
    const float* W1l = (const float*)d_in[2];
    const float* b1  = (const float*)d_in[3];
    const float* W1r = (const float*)d_in[4];
    const float* W2l = (const float*)d_in[5];
    const float* b2  = (const float*)d_in[6];
    const float* W2r = (const float*)d_in[7];
    float* out = (float*)d_out;

    const int E = in_sizes[1] / 2;

    k_zero<<<(N_NODES + 255) / 256, 256>>>();
    k_fill<<<(E + 255) / 256, 256>>>(ei, E);

    k_agg1<<<(N_NODES + 7) / 8, 256>>>(x);
    k_gemm1<<<(N_NODES + 127) / 128, 256>>>(x, W1l, b1, W1r);

    k_gemm2<<<(N_NODES + 127) / 128, 256>>>(W2l, b2, W2r, out);
    k_agg2<<<(N_NODES + 7) / 8, 256>>>(out);
}

// round 15
// speedup vs baseline: 1.6362x; 1.0145x over previous
#include <cuda_runtime.h>

#define N_NODES 50000
#define IN_C   128
#define HID_C  128
#define OUT_C  64
#define CAP    128          // neighbor bucket capacity (Poisson mean 16 -> safe)

// ---------------------------------------------------------------------------
// Device-global scratch (no allocations allowed)
// ---------------------------------------------------------------------------
__device__ int   g_cnt [N_NODES];             // per-node neighbor count
__device__ int   g_adj [N_NODES * CAP];       // bucketed adjacency (src ids)
__device__ float g_mean[N_NODES * IN_C];      // mean of neighbor x (tf32-rounded)
__device__ float g_xt  [N_NODES * IN_C];      // x, tf32-rounded
__device__ float g_w1  [256 * 128];           // [W1_l ; W1_r], tf32-rounded
__device__ float g_w2  [128 * 128];           // [W2_l | W2_r], tf32-rounded
__device__ float g_h   [N_NODES * HID_C];     // layer-1 activations (tf32-rounded)
__device__ float g_t   [N_NODES * OUT_C];     // h @ W2_l (full fp32)

// ---------------------------------------------------------------------------
// TF32 helper
// ---------------------------------------------------------------------------
__device__ __forceinline__ unsigned f2tf32(float f) {
    unsigned u;
    asm("cvt.rna.tf32.f32 %0, %1;" : "=r"(u) : "f"(f));
    return u;
}
__device__ __forceinline__ float rnd32(float f) { return __uint_as_float(f2tf32(f)); }

// ---------------------------------------------------------------------------
// k_cvt: pre-round x + weights to tf32; also zeroes g_cnt (replaces k_zero).
// ---------------------------------------------------------------------------
__global__ void k_cvt(const float* __restrict__ x,
                      const float* __restrict__ W1l, const float* __restrict__ W1r,
                      const float* __restrict__ W2l, const float* __restrict__ W2r) {
    const int NX4  = N_NODES * IN_C / 4;   // 1,600,000
    const int NW14 = 256 * 128 / 4;        // 8192
    const int NW24 = 128 * 128 / 4;        // 4096
    const int total = NX4 + NW14 + NW24;
    const int stride = gridDim.x * blockDim.x;
    for (int i = blockIdx.x * blockDim.x + threadIdx.x; i < total; i += stride) {
        float4 v;
        float4* dst;
        if (i < NX4) {
            v = ((const float4*)x)[i];
            dst = ((float4*)g_xt) + i;
        } else if (i < NX4 + NW14) {
            int j = i - NX4;
            int e = j * 4, r = e >> 7, c = e & 127;
            const float* s = (r < 128) ? (W1l + r * 128 + c) : (W1r + (r - 128) * 128 + c);
            v = *(const float4*)s;
            dst = ((float4*)g_w1) + j;
        } else {
            int j = i - NX4 - NW14;
            int e = j * 4, r = e >> 7, c = e & 127;
            const float* s = (c < 64) ? (W2l + r * 64 + c) : (W2r + r * 64 + (c - 64));
            v = *(const float4*)s;
            dst = ((float4*)g_w2) + j;
        }
        float4 o;
        o.x = rnd32(v.x); o.y = rnd32(v.y); o.z = rnd32(v.z); o.w = rnd32(v.w);
        *dst = o;
    }
    for (int i = blockIdx.x * blockDim.x + threadIdx.x; i < N_NODES; i += stride)
        g_cnt[i] = 0;
}

// ---------------------------------------------------------------------------
__global__ void k_fill(const int* __restrict__ ei, int E) {
    int e = blockIdx.x * blockDim.x + threadIdx.x;
    if (e >= E) return;
    int s = ei[e];
    int d = ei[E + e];
    int pos = atomicAdd(&g_cnt[d], 1);
    if (pos < CAP) g_adj[d * CAP + pos] = s;
}

// ---------------------------------------------------------------------------
// Aggregation 1: one warp per node; epilogue stores tf32-rounded mean.
// ---------------------------------------------------------------------------
__global__ void k_agg1(const float* __restrict__ x) {
    int node = blockIdx.x * (blockDim.x >> 5) + (threadIdx.x >> 5);
    int lane = threadIdx.x & 31;
    if (node >= N_NODES) return;

    int deg = min(g_cnt[node], CAP);
    const int* adj = g_adj + node * CAP;

    float4 a0 = make_float4(0.f, 0.f, 0.f, 0.f);
    float4 a1 = make_float4(0.f, 0.f, 0.f, 0.f);
    float4 a2 = make_float4(0.f, 0.f, 0.f, 0.f);
    float4 a3 = make_float4(0.f, 0.f, 0.f, 0.f);

    int p = 0;
    for (; p + 8 <= deg; p += 8) {
        int4 i0 = *(const int4*)(adj + p);
        int4 i1 = *(const int4*)(adj + p + 4);
        float4 v0 = ((const float4*)(x + (size_t)i0.x * IN_C))[lane];
        float4 v1 = ((const float4*)(x + (size_t)i0.y * IN_C))[lane];
        float4 v2 = ((const float4*)(x + (size_t)i0.z * IN_C))[lane];
        float4 v3 = ((const float4*)(x + (size_t)i0.w * IN_C))[lane];
        float4 v4 = ((const float4*)(x + (size_t)i1.x * IN_C))[lane];
        float4 v5 = ((const float4*)(x + (size_t)i1.y * IN_C))[lane];
        float4 v6 = ((const float4*)(x + (size_t)i1.z * IN_C))[lane];
        float4 v7 = ((const float4*)(x + (size_t)i1.w * IN_C))[lane];
        a0.x += v0.x; a0.y += v0.y; a0.z += v0.z; a0.w += v0.w;
        a1.x += v1.x; a1.y += v1.y; a1.z += v1.z; a1.w += v1.w;
        a2.x += v2.x; a2.y += v2.y; a2.z += v2.z; a2.w += v2.w;
        a3.x += v3.x; a3.y += v3.y; a3.z += v3.z; a3.w += v3.w;
        a0.x += v4.x; a0.y += v4.y; a0.z += v4.z; a0.w += v4.w;
        a1.x += v5.x; a1.y += v5.y; a1.z += v5.z; a1.w += v5.w;
        a2.x += v6.x; a2.y += v6.y; a2.z += v6.z; a2.w += v6.w;
        a3.x += v7.x; a3.y += v7.y; a3.z += v7.z; a3.w += v7.w;
    }
    if (p + 4 <= deg) {
        int4 i0 = *(const int4*)(adj + p);
        float4 v0 = ((const float4*)(x + (size_t)i0.x * IN_C))[lane];
        float4 v1 = ((const float4*)(x + (size_t)i0.y * IN_C))[lane];
        float4 v2 = ((const float4*)(x + (size_t)i0.z * IN_C))[lane];
        float4 v3 = ((const float4*)(x + (size_t)i0.w * IN_C))[lane];
        a0.x += v0.x; a0.y += v0.y; a0.z += v0.z; a0.w += v0.w;
        a1.x += v1.x; a1.y += v1.y; a1.z += v1.z; a1.w += v1.w;
        a2.x += v2.x; a2.y += v2.y; a2.z += v2.z; a2.w += v2.w;
        a3.x += v3.x; a3.y += v3.y; a3.z += v3.z; a3.w += v3.w;
        p += 4;
    }
    for (; p < deg; p++) {
        int s = adj[p];
        float4 v = ((const float4*)(x + (size_t)s * IN_C))[lane];
        a0.x += v.x; a0.y += v.y; a0.z += v.z; a0.w += v.w;
    }
    float4 acc;
    acc.x = (a0.x + a1.x) + (a2.x + a3.x);
    acc.y = (a0.y + a1.y) + (a2.y + a3.y);
    acc.z = (a0.z + a1.z) + (a2.z + a3.z);
    acc.w = (a0.w + a1.w) + (a2.w + a3.w);
    float inv = (deg > 0) ? 1.f / (float)deg : 0.f;
    acc.x = rnd32(acc.x * inv);
    acc.y = rnd32(acc.y * inv);
    acc.z = rnd32(acc.z * inv);
    acc.w = rnd32(acc.w * inv);
    ((float4*)(g_mean + (size_t)node * IN_C))[lane] = acc;
}

// ---------------------------------------------------------------------------
// MMA + cp.async helpers
// ---------------------------------------------------------------------------
__device__ __forceinline__ void mma_tf32(float d[4], const unsigned a[4],
                                         const unsigned b[2]) {
    asm volatile(
        "mma.sync.aligned.m16n8k8.row.col.f32.tf32.tf32.f32 "
        "{%0,%1,%2,%3}, {%4,%5,%6,%7}, {%8,%9}, {%0,%1,%2,%3};"
        : "+f"(d[0]), "+f"(d[1]), "+f"(d[2]), "+f"(d[3])
        : "r"(a[0]), "r"(a[1]), "r"(a[2]), "r"(a[3]), "r"(b[0]), "r"(b[1]));
}
__device__ __forceinline__ unsigned sptr(const void* p) {
    return (unsigned)__cvta_generic_to_shared(p);
}
__device__ __forceinline__ void cp16(unsigned d, const void* s) {
    asm volatile("cp.async.cg.shared.global [%0], [%1], 16;" :: "r"(d), "l"(s) : "memory");
}
__device__ __forceinline__ void cp_commit() {
    asm volatile("cp.async.commit_group;" ::: "memory");
}
__device__ __forceinline__ void cp_wait1() {
    asm volatile("cp.async.wait_group 1;" ::: "memory");
}

#define ASTR 20    // A smem row stride (m-major, 16 k + 4 pad): loads conflict-free
#define BSTR 136   // B smem row stride (k-major): 136 mod 32 = 8, conflict-free

// ---------------------------------------------------------------------------
// GEMM 1 (TF32, cp.async fills): h = relu( [mean | x] @ g_w1 + b1 )  K=256
// A m-major [128][ASTR], B k-major [16][BSTR]; 128x128 tile, 8 warps 2x4.
// ---------------------------------------------------------------------------
__global__ __launch_bounds__(256) void k_gemm1(const float* __restrict__ b1) {
    __shared__ unsigned As[2][128][ASTR];
    __shared__ unsigned Bs[2][16][BSTR];

    const int tid  = threadIdx.x;
    const int brow = blockIdx.x * 128;

    const int am  = tid & 127;
    const int akb = (tid >> 7) * 8;
    const int ra  = min(brow + am, N_NODES - 1);
    const int bkr = tid >> 4;
    const int bnc = (tid & 15) * 8;

    const int wid  = tid >> 5;
    const int lane = tid & 31;
    const int g    = lane >> 2;
    const int t    = lane & 3;
    const int m0   = (wid >> 2) * 64;
    const int n0   = (wid & 3) * 32;

    float acc[4][4][4];
#pragma unroll
    for (int mt = 0; mt < 4; mt++)
#pragma unroll
        for (int nt = 0; nt < 4; nt++)
#pragma unroll
            for (int r = 0; r < 4; r++) acc[mt][nt][r] = 0.f;

    auto issue = [&](int buf, int kc) {
        int kg = kc + akb;
        const float* srcA = (kg < 128) ? (g_mean + (size_t)ra * 128 + kg)
                                       : (g_xt + (size_t)ra * 128 + (kg - 128));
        unsigned da = sptr(&As[buf][am][akb]);
        cp16(da, srcA);
        cp16(da + 16, srcA + 4);
        const float* srcB = g_w1 + (size_t)(kc + bkr) * 128 + bnc;
        unsigned db = sptr(&Bs[buf][bkr][bnc]);
        cp16(db, srcB);
        cp16(db + 16, srcB + 4);
    };

    issue(0, 0);
    cp_commit();

    for (int i = 0; i < 16; i++) {
        if (i + 1 < 16) issue((i + 1) & 1, (i + 1) * 16);
        cp_commit();
        cp_wait1();
        __syncthreads();

        const int buf = i & 1;
#pragma unroll
        for (int kk = 0; kk < 16; kk += 8) {
            unsigned afr[4][4];
#pragma unroll
            for (int mt = 0; mt < 4; mt++) {
                int mr = m0 + mt * 16 + g;
                afr[mt][0] = As[buf][mr][kk + t];
                afr[mt][1] = As[buf][mr + 8][kk + t];
                afr[mt][2] = As[buf][mr][kk + t + 4];
                afr[mt][3] = As[buf][mr + 8][kk + t + 4];
            }
            unsigned bfr[4][2];
#pragma unroll
            for (int nt = 0; nt < 4; nt++) {
                int nr = n0 + nt * 8 + g;
                bfr[nt][0] = Bs[buf][kk + t][nr];
                bfr[nt][1] = Bs[buf][kk + t + 4][nr];
            }
#pragma unroll
            for (int mt = 0; mt < 4; mt++)
#pragma unroll
                for (int nt = 0; nt < 4; nt++)
                    mma_tf32(acc[mt][nt], afr[mt], bfr[nt]);
        }
        __syncthreads();
    }

#pragma unroll
    for (int nt = 0; nt < 4; nt++) {
        int c = n0 + nt * 8 + 2 * t;
        float2 bb = *(const float2*)(b1 + c);
#pragma unroll
        for (int mt = 0; mt < 4; mt++) {
            int r0 = brow + m0 + mt * 16 + g;
            if (r0 < N_NODES) {
                float2 o;
                o.x = rnd32(fmaxf(acc[mt][nt][0] + bb.x, 0.f));
                o.y = rnd32(fmaxf(acc[mt][nt][1] + bb.y, 0.f));
                *(float2*)(g_h + (size_t)r0 * 128 + c) = o;
            }
            int r1 = r0 + 8;
            if (r1 < N_NODES) {
                float2 o;
                o.x = rnd32(fmaxf(acc[mt][nt][2] + bb.x, 0.f));
                o.y = rnd32(fmaxf(acc[mt][nt][3] + bb.y, 0.f));
                *(float2*)(g_h + (size_t)r1 * 128 + c) = o;
            }
        }
    }
}

// ---------------------------------------------------------------------------
// GEMM 2 (TF32, cp.async fills): t = h @ W2_l ; out = h @ W2_r + b2  K=128
// ---------------------------------------------------------------------------
__global__ __launch_bounds__(256) void k_gemm2(const float* __restrict__ b2,
                                               float* __restrict__ out) {
    __shared__ unsigned As[2][128][ASTR];
    __shared__ unsigned Bs[2][16][BSTR];

    const int tid  = threadIdx.x;
    const int brow = blockIdx.x * 128;

    const int am  = tid & 127;
    const int akb = (tid >> 7) * 8;
    const int ra  = min(brow + am, N_NODES - 1);
    const int bkr = tid >> 4;
    const int bnc = (tid & 15) * 8;

    const int wid  = tid >> 5;
    const int lane = tid & 31;
    const int g    = lane >> 2;
    const int t    = lane & 3;
    const int m0   = (wid >> 2) * 64;
    const int n0   = (wid & 3) * 32;

    float acc[4][4][4];
#pragma unroll
    for (int mt = 0; mt < 4; mt++)
#pragma unroll
        for (int nt = 0; nt < 4; nt++)
#pragma unroll
            for (int r = 0; r < 4; r++) acc[mt][nt][r] = 0.f;

    auto issue = [&](int buf, int kc) {
        const float* srcA = g_h + (size_t)ra * 128 + kc + akb;
        unsigned da = sptr(&As[buf][am][akb]);
        cp16(da, srcA);
        cp16(da + 16, srcA + 4);
        const float* srcB = g_w2 + (size_t)(kc + bkr) * 128 + bnc;
        unsigned db = sptr(&Bs[buf][bkr][bnc]);
        cp16(db, srcB);
        cp16(db + 16, srcB + 4);
    };

    issue(0, 0);
    cp_commit();

    for (int i = 0; i < 8; i++) {
        if (i + 1 < 8) issue((i + 1) & 1, (i + 1) * 16);
        cp_commit();
        cp_wait1();
        __syncthreads();

        const int buf = i & 1;
#pragma unroll
        for (int kk = 0; kk < 16; kk += 8) {
            unsigned afr[4][4];
#pragma unroll
            for (int mt = 0; mt < 4; mt++) {
                int mr = m0 + mt * 16 + g;
                afr[mt][0] = As[buf][mr][kk + t];
                afr[mt][1] = As[buf][mr + 8][kk + t];
                afr[mt][2] = As[buf][mr][kk + t + 4];
                afr[mt][3] = As[buf][mr + 8][kk + t + 4];
            }
            unsigned bfr[4][2];
#pragma unroll
            for (int nt = 0; nt < 4; nt++) {
                int nr = n0 + nt * 8 + g;
                bfr[nt][0] = Bs[buf][kk + t][nr];
                bfr[nt][1] = Bs[buf][kk + t + 4][nr];
            }
#pragma unroll
            for (int mt = 0; mt < 4; mt++)
#pragma unroll
                for (int nt = 0; nt < 4; nt++)
                    mma_tf32(acc[mt][nt], afr[mt], bfr[nt]);
        }
        __syncthreads();
    }

#pragma unroll
    for (int nt = 0; nt < 4; nt++) {
        int c = n0 + nt * 8 + 2 * t;
        if (c < 64) {
#pragma unroll
            for (int mt = 0; mt < 4; mt++) {
                int r0 = brow + m0 + mt * 16 + g;
                if (r0 < N_NODES)
                    *(float2*)(g_t + (size_t)r0 * 64 + c) =
                        make_float2(acc[mt][nt][0], acc[mt][nt][1]);
                int r1 = r0 + 8;
                if (r1 < N_NODES)
                    *(float2*)(g_t + (size_t)r1 * 64 + c) =
                        make_float2(acc[mt][nt][2], acc[mt][nt][3]);
            }
        } else {
            int co = c - 64;
            float2 bb = *(const float2*)(b2 + co);
#pragma unroll
            for (int mt = 0; mt < 4; mt++) {
                int r0 = brow + m0 + mt * 16 + g;
                if (r0 < N_NODES)
                    *(float2*)(out + (size_t)r0 * 64 + co) =
                        make_float2(acc[mt][nt][0] + bb.x, acc[mt][nt][1] + bb.y);
                int r1 = r0 + 8;
                if (r1 < N_NODES)
                    *(float2*)(out + (size_t)r1 * 64 + co) =
                        make_float2(acc[mt][nt][2] + bb.x, acc[mt][nt][3] + bb.y);
            }
        }
    }
}

// ---------------------------------------------------------------------------
// Aggregation 2 + final: out[n] += mean_{s in N(n)} t[s] (64 f32/node)
// ---------------------------------------------------------------------------
__global__ void k_agg2(float* __restrict__ out) {
    int node = blockIdx.x * (blockDim.x >> 5) + (threadIdx.x >> 5);
    int lane = threadIdx.x & 31;
    if (node >= N_NODES) return;

    int deg = min(g_cnt[node], CAP);
    const int* adj = g_adj + node * CAP;

    float2 a0 = make_float2(0.f, 0.f);
    float2 a1 = make_float2(0.f, 0.f);
    float2 a2 = make_float2(0.f, 0.f);
    float2 a3 = make_float2(0.f, 0.f);

    int p = 0;
    for (; p + 8 <= deg; p += 8) {
        int4 i0 = *(const int4*)(adj + p);
        int4 i1 = *(const int4*)(adj + p + 4);
        float2 v0 = ((const float2*)(g_t + (size_t)i0.x * OUT_C))[lane];
        float2 v1 = ((const float2*)(g_t + (size_t)i0.y * OUT_C))[lane];
        float2 v2 = ((const float2*)(g_t + (size_t)i0.z * OUT_C))[lane];
        float2 v3 = ((const float2*)(g_t + (size_t)i0.w * OUT_C))[lane];
        float2 v4 = ((const float2*)(g_t + (size_t)i1.x * OUT_C))[lane];
        float2 v5 = ((const float2*)(g_t + (size_t)i1.y * OUT_C))[lane];
        float2 v6 = ((const float2*)(g_t + (size_t)i1.z * OUT_C))[lane];
        float2 v7 = ((const float2*)(g_t + (size_t)i1.w * OUT_C))[lane];
        a0.x += v0.x; a0.y += v0.y;
        a1.x += v1.x; a1.y += v1.y;
        a2.x += v2.x; a2.y += v2.y;
        a3.x += v3.x; a3.y += v3.y;
        a0.x += v4.x; a0.y += v4.y;
        a1.x += v5.x; a1.y += v5.y;
        a2.x += v6.x; a2.y += v6.y;
        a3.x += v7.x; a3.y += v7.y;
    }
    if (p + 4 <= deg) {
        int4 i0 = *(const int4*)(adj + p);
        float2 v0 = ((const float2*)(g_t + (size_t)i0.x * OUT_C))[lane];
        float2 v1 = ((const float2*)(g_t + (size_t)i0.y * OUT_C))[lane];
        float2 v2 = ((const float2*)(g_t + (size_t)i0.z * OUT_C))[lane];
        float2 v3 = ((const float2*)(g_t + (size_t)i0.w * OUT_C))[lane];
        a0.x += v0.x; a0.y += v0.y;
        a1.x += v1.x; a1.y += v1.y;
        a2.x += v2.x; a2.y += v2.y;
        a3.x += v3.x; a3.y += v3.y;
        p += 4;
    }
    for (; p < deg; p++) {
        int s = adj[p];
        float2 v = ((const float2*)(g_t + (size_t)s * OUT_C))[lane];
        a0.x += v.x; a0.y += v.y;
    }
    float inv = (deg > 0) ? 1.f / (float)deg : 0.f;
    float sx = ((a0.x + a1.x) + (a2.x + a3.x)) * inv;
    float sy = ((a0.y + a1.y) + (a2.y + a3.y)) * inv;

    float2* o = (float2*)(out + (size_t)node * OUT_C) + lane;
    float2 cur = *o;
    cur.x += sx;
    cur.y += sy;
    *o = cur;
}

// ---------------------------------------------------------------------------
extern "C" void kernel_launch(void* const* d_in, const int* in_sizes, int n_in,
                              void* d_out, int out_size) {
    const float* x   = (const float*)d_in[0];
    const int*   ei  = (const int*)d_in[1];     // int32 (JAX default x64 off)
    const float* W1l = (const float*)d_in[2];
    const float* b1  = (const float*)d_in[3];
    const float* W1r = (const float*)d_in[4];
    const float* W2l = (const float*)d_in[5];
    const float* b2  = (const float*)d_in[6];
    const float* W2r = (const float*)d_in[7];
    float* out = (float*)d_out;

    const int E = in_sizes[1] / 2;

    k_cvt<<<1024, 256>>>(x, W1l, W1r, W2l, W2r);   // rounds x/weights, zeroes g_cnt
    k_fill<<<(E + 255) / 256, 256>>>(ei, E);

    k_agg1<<<(N_NODES + 7) / 8, 256>>>(x);
    k_gemm1<<<(N_NODES + 127) / 128, 256>>>(b1);

    k_gemm2<<<(N_NODES + 127) / 128, 256>>>(b2, out);
    k_agg2<<<(N_NODES + 7) / 8, 256>>>(out);
}

// round 16
// speedup vs baseline: 1.6577x; 1.0132x over previous
#include <cuda_runtime.h>

#define N_NODES 50000
#define IN_C   128
#define HID_C  128
#define OUT_C  64
#define CAP    128          // neighbor bucket capacity (Poisson mean 16 -> safe)

// ---------------------------------------------------------------------------
// Device-global scratch (no allocations allowed)
// ---------------------------------------------------------------------------
__device__ int   g_cnt [N_NODES];
__device__ int   g_adj [N_NODES * CAP];
__device__ float g_mean[N_NODES * IN_C];      // mean of neighbor x (tf32-rounded)
__device__ float g_xt  [N_NODES * IN_C];      // x, tf32-rounded
__device__ float g_w1  [256 * 128];           // [W1_l ; W1_r], tf32-rounded
__device__ float g_w2  [128 * 128];           // [W2_l | W2_r], tf32-rounded
__device__ float g_h   [N_NODES * HID_C];     // layer-1 activations (tf32-rounded)
__device__ float g_t   [N_NODES * OUT_C];     // h @ W2_l (full fp32)

// ---------------------------------------------------------------------------
__device__ __forceinline__ unsigned f2tf32(float f) {
    unsigned u;
    asm("cvt.rna.tf32.f32 %0, %1;" : "=r"(u) : "f"(f));
    return u;
}
__device__ __forceinline__ float rnd32(float f) { return __uint_as_float(f2tf32(f)); }

// ---------------------------------------------------------------------------
// k_cvt: pre-round x + weights to tf32; also zeroes g_cnt.
// ---------------------------------------------------------------------------
__global__ void k_cvt(const float* __restrict__ x,
                      const float* __restrict__ W1l, const float* __restrict__ W1r,
                      const float* __restrict__ W2l, const float* __restrict__ W2r) {
    const int NX4  = N_NODES * IN_C / 4;
    const int NW14 = 256 * 128 / 4;
    const int NW24 = 128 * 128 / 4;
    const int total = NX4 + NW14 + NW24;
    const int stride = gridDim.x * blockDim.x;
    for (int i = blockIdx.x * blockDim.x + threadIdx.x; i < total; i += stride) {
        float4 v;
        float4* dst;
        if (i < NX4) {
            v = ((const float4*)x)[i];
            dst = ((float4*)g_xt) + i;
        } else if (i < NX4 + NW14) {
            int j = i - NX4;
            int e = j * 4, r = e >> 7, c = e & 127;
            const float* s = (r < 128) ? (W1l + r * 128 + c) : (W1r + (r - 128) * 128 + c);
            v = *(const float4*)s;
            dst = ((float4*)g_w1) + j;
        } else {
            int j = i - NX4 - NW14;
            int e = j * 4, r = e >> 7, c = e & 127;
            const float* s = (c < 64) ? (W2l + r * 64 + c) : (W2r + r * 64 + (c - 64));
            v = *(const float4*)s;
            dst = ((float4*)g_w2) + j;
        }
        float4 o;
        o.x = rnd32(v.x); o.y = rnd32(v.y); o.z = rnd32(v.z); o.w = rnd32(v.w);
        *dst = o;
    }
    for (int i = blockIdx.x * blockDim.x + threadIdx.x; i < N_NODES; i += stride)
        g_cnt[i] = 0;
}

// ---------------------------------------------------------------------------
__global__ void k_fill(const int* __restrict__ ei, int E) {
    int e = blockIdx.x * blockDim.x + threadIdx.x;
    if (e >= E) return;
    int s = ei[e];
    int d = ei[E + e];
    int pos = atomicAdd(&g_cnt[d], 1);
    if (pos < CAP) g_adj[d * CAP + pos] = s;
}

// ---------------------------------------------------------------------------
// Aggregation 1 (at LTS floor): one warp per node; stores tf32-rounded mean.
// ---------------------------------------------------------------------------
__global__ void k_agg1(const float* __restrict__ x) {
    int node = blockIdx.x * (blockDim.x >> 5) + (threadIdx.x >> 5);
    int lane = threadIdx.x & 31;
    if (node >= N_NODES) return;

    int deg = min(g_cnt[node], CAP);
    const int* adj = g_adj + node * CAP;

    float4 a0 = make_float4(0.f, 0.f, 0.f, 0.f);
    float4 a1 = make_float4(0.f, 0.f, 0.f, 0.f);
    float4 a2 = make_float4(0.f, 0.f, 0.f, 0.f);
    float4 a3 = make_float4(0.f, 0.f, 0.f, 0.f);

    int p = 0;
    for (; p + 8 <= deg; p += 8) {
        int4 i0 = *(const int4*)(adj + p);
        int4 i1 = *(const int4*)(adj + p + 4);
        float4 v0 = ((const float4*)(x + (size_t)i0.x * IN_C))[lane];
        float4 v1 = ((const float4*)(x + (size_t)i0.y * IN_C))[lane];
        float4 v2 = ((const float4*)(x + (size_t)i0.z * IN_C))[lane];
        float4 v3 = ((const float4*)(x + (size_t)i0.w * IN_C))[lane];
        float4 v4 = ((const float4*)(x + (size_t)i1.x * IN_C))[lane];
        float4 v5 = ((const float4*)(x + (size_t)i1.y * IN_C))[lane];
        float4 v6 = ((const float4*)(x + (size_t)i1.z * IN_C))[lane];
        float4 v7 = ((const float4*)(x + (size_t)i1.w * IN_C))[lane];
        a0.x += v0.x; a0.y += v0.y; a0.z += v0.z; a0.w += v0.w;
        a1.x += v1.x; a1.y += v1.y; a1.z += v1.z; a1.w += v1.w;
        a2.x += v2.x; a2.y += v2.y; a2.z += v2.z; a2.w += v2.w;
        a3.x += v3.x; a3.y += v3.y; a3.z += v3.z; a3.w += v3.w;
        a0.x += v4.x; a0.y += v4.y; a0.z += v4.z; a0.w += v4.w;
        a1.x += v5.x; a1.y += v5.y; a1.z += v5.z; a1.w += v5.w;
        a2.x += v6.x; a2.y += v6.y; a2.z += v6.z; a2.w += v6.w;
        a3.x += v7.x; a3.y += v7.y; a3.z += v7.z; a3.w += v7.w;
    }
    if (p + 4 <= deg) {
        int4 i0 = *(const int4*)(adj + p);
        float4 v0 = ((const float4*)(x + (size_t)i0.x * IN_C))[lane];
        float4 v1 = ((const float4*)(x + (size_t)i0.y * IN_C))[lane];
        float4 v2 = ((const float4*)(x + (size_t)i0.z * IN_C))[lane];
        float4 v3 = ((const float4*)(x + (size_t)i0.w * IN_C))[lane];
        a0.x += v0.x; a0.y += v0.y; a0.z += v0.z; a0.w += v0.w;
        a1.x += v1.x; a1.y += v1.y; a1.z += v1.z; a1.w += v1.w;
        a2.x += v2.x; a2.y += v2.y; a2.z += v2.z; a2.w += v2.w;
        a3.x += v3.x; a3.y += v3.y; a3.z += v3.z; a3.w += v3.w;
        p += 4;
    }
    for (; p < deg; p++) {
        int s = adj[p];
        float4 v = ((const float4*)(x + (size_t)s * IN_C))[lane];
        a0.x += v.x; a0.y += v.y; a0.z += v.z; a0.w += v.w;
    }
    float4 acc;
    acc.x = (a0.x + a1.x) + (a2.x + a3.x);
    acc.y = (a0.y + a1.y) + (a2.y + a3.y);
    acc.z = (a0.z + a1.z) + (a2.z + a3.z);
    acc.w = (a0.w + a1.w) + (a2.w + a3.w);
    float inv = (deg > 0) ? 1.f / (float)deg : 0.f;
    acc.x = rnd32(acc.x * inv);
    acc.y = rnd32(acc.y * inv);
    acc.z = rnd32(acc.z * inv);
    acc.w = rnd32(acc.w * inv);
    ((float4*)(g_mean + (size_t)node * IN_C))[lane] = acc;
}

// ---------------------------------------------------------------------------
// MMA + cp.async helpers
// ---------------------------------------------------------------------------
__device__ __forceinline__ void mma_tf32(float d[4], const unsigned a[4],
                                         const unsigned b[2]) {
    asm volatile(
        "mma.sync.aligned.m16n8k8.row.col.f32.tf32.tf32.f32 "
        "{%0,%1,%2,%3}, {%4,%5,%6,%7}, {%8,%9}, {%0,%1,%2,%3};"
        : "+f"(d[0]), "+f"(d[1]), "+f"(d[2]), "+f"(d[3])
        : "r"(a[0]), "r"(a[1]), "r"(a[2]), "r"(a[3]), "r"(b[0]), "r"(b[1]));
}
__device__ __forceinline__ unsigned sptr(const void* p) {
    return (unsigned)__cvta_generic_to_shared(p);
}
__device__ __forceinline__ void cp16(unsigned d, const void* s) {
    asm volatile("cp.async.cg.shared.global [%0], [%1], 16;" :: "r"(d), "l"(s) : "memory");
}
__device__ __forceinline__ void cp_commit() {
    asm volatile("cp.async.commit_group;" ::: "memory");
}
__device__ __forceinline__ void cp_wait2() {
    asm volatile("cp.async.wait_group 2;" ::: "memory");
}

#define ASTR 20    // A smem row stride (m-major, 16 k + 4 pad)
#define BSTR 136   // B smem row stride (k-major)
#define NSTAGE 4
#define A_WORDS (128 * ASTR)      // per stage
#define B_WORDS (16 * BSTR)       // per stage
#define DSMEM_BYTES (NSTAGE * (A_WORDS + B_WORDS) * 4)   // 75,776 B

extern __shared__ unsigned dyn_smem[];

// ---------------------------------------------------------------------------
// GEMM 1 (TF32, 4-stage cp.async): h = relu( [mean | x] @ g_w1 + b1 )  K=256
// ---------------------------------------------------------------------------
__global__ __launch_bounds__(256) void k_gemm1(const float* __restrict__ b1) {
    unsigned* As = dyn_smem;                       // [NSTAGE][128][ASTR]
    unsigned* Bs = dyn_smem + NSTAGE * A_WORDS;    // [NSTAGE][16][BSTR]

    const int tid  = threadIdx.x;
    const int brow = blockIdx.x * 128;

    const int am  = tid & 127;
    const int akb = (tid >> 7) * 8;
    const int ra  = min(brow + am, N_NODES - 1);
    const int bkr = tid >> 4;
    const int bnc = (tid & 15) * 8;

    const int wid  = tid >> 5;
    const int lane = tid & 31;
    const int g    = lane >> 2;
    const int t    = lane & 3;
    const int m0   = (wid >> 2) * 64;
    const int n0   = (wid & 3) * 32;

    float acc[4][4][4];
#pragma unroll
    for (int mt = 0; mt < 4; mt++)
#pragma unroll
        for (int nt = 0; nt < 4; nt++)
#pragma unroll
            for (int r = 0; r < 4; r++) acc[mt][nt][r] = 0.f;

    auto issue = [&](int st, int kc) {
        int kg = kc + akb;
        const float* srcA = (kg < 128) ? (g_mean + (size_t)ra * 128 + kg)
                                       : (g_xt + (size_t)ra * 128 + (kg - 128));
        unsigned da = sptr(As + st * A_WORDS + am * ASTR + akb);
        cp16(da, srcA);
        cp16(da + 16, srcA + 4);
        const float* srcB = g_w1 + (size_t)(kc + bkr) * 128 + bnc;
        unsigned db = sptr(Bs + st * B_WORDS + bkr * BSTR + bnc);
        cp16(db, srcB);
        cp16(db + 16, srcB + 4);
    };

    const int T = 16;
#pragma unroll
    for (int s = 0; s < 3; s++) { issue(s, s * 16); cp_commit(); }

    for (int i = 0; i < T; i++) {
        cp_wait2();
        __syncthreads();      // stage i ready; all warps done with buf (i+3)%4's old data
        if (i + 3 < T) issue((i + 3) & 3, (i + 3) * 16);
        cp_commit();

        const unsigned* Ab = As + (i & 3) * A_WORDS;
        const unsigned* Bb = Bs + (i & 3) * B_WORDS;
#pragma unroll
        for (int kk = 0; kk < 16; kk += 8) {
            unsigned afr[4][4];
#pragma unroll
            for (int mt = 0; mt < 4; mt++) {
                int mr = m0 + mt * 16 + g;
                afr[mt][0] = Ab[mr * ASTR + kk + t];
                afr[mt][1] = Ab[(mr + 8) * ASTR + kk + t];
                afr[mt][2] = Ab[mr * ASTR + kk + t + 4];
                afr[mt][3] = Ab[(mr + 8) * ASTR + kk + t + 4];
            }
            unsigned bfr[4][2];
#pragma unroll
            for (int nt = 0; nt < 4; nt++) {
                int nr = n0 + nt * 8 + g;
                bfr[nt][0] = Bb[(kk + t) * BSTR + nr];
                bfr[nt][1] = Bb[(kk + t + 4) * BSTR + nr];
            }
#pragma unroll
            for (int mt = 0; mt < 4; mt++)
#pragma unroll
                for (int nt = 0; nt < 4; nt++)
                    mma_tf32(acc[mt][nt], afr[mt], bfr[nt]);
        }
    }

#pragma unroll
    for (int nt = 0; nt < 4; nt++) {
        int c = n0 + nt * 8 + 2 * t;
        float2 bb = *(const float2*)(b1 + c);
#pragma unroll
        for (int mt = 0; mt < 4; mt++) {
            int r0 = brow + m0 + mt * 16 + g;
            if (r0 < N_NODES) {
                float2 o;
                o.x = rnd32(fmaxf(acc[mt][nt][0] + bb.x, 0.f));
                o.y = rnd32(fmaxf(acc[mt][nt][1] + bb.y, 0.f));
                *(float2*)(g_h + (size_t)r0 * 128 + c) = o;
            }
            int r1 = r0 + 8;
            if (r1 < N_NODES) {
                float2 o;
                o.x = rnd32(fmaxf(acc[mt][nt][2] + bb.x, 0.f));
                o.y = rnd32(fmaxf(acc[mt][nt][3] + bb.y, 0.f));
                *(float2*)(g_h + (size_t)r1 * 128 + c) = o;
            }
        }
    }
}

// ---------------------------------------------------------------------------
// GEMM 2 (TF32, 4-stage cp.async): t = h @ W2_l ; out = h @ W2_r + b2  K=128
// ---------------------------------------------------------------------------
__global__ __launch_bounds__(256) void k_gemm2(const float* __restrict__ b2,
                                               float* __restrict__ out) {
    unsigned* As = dyn_smem;
    unsigned* Bs = dyn_smem + NSTAGE * A_WORDS;

    const int tid  = threadIdx.x;
    const int brow = blockIdx.x * 128;

    const int am  = tid & 127;
    const int akb = (tid >> 7) * 8;
    const int ra  = min(brow + am, N_NODES - 1);
    const int bkr = tid >> 4;
    const int bnc = (tid & 15) * 8;

    const int wid  = tid >> 5;
    const int lane = tid & 31;
    const int g    = lane >> 2;
    const int t    = lane & 3;
    const int m0   = (wid >> 2) * 64;
    const int n0   = (wid & 3) * 32;

    float acc[4][4][4];
#pragma unroll
    for (int mt = 0; mt < 4; mt++)
#pragma unroll
        for (int nt = 0; nt < 4; nt++)
#pragma unroll
            for (int r = 0; r < 4; r++) acc[mt][nt][r] = 0.f;

    auto issue = [&](int st, int kc) {
        const float* srcA = g_h + (size_t)ra * 128 + kc + akb;
        unsigned da = sptr(As + st * A_WORDS + am * ASTR + akb);
        cp16(da, srcA);
        cp16(da + 16, srcA + 4);
        const float* srcB = g_w2 + (size_t)(kc + bkr) * 128 + bnc;
        unsigned db = sptr(Bs + st * B_WORDS + bkr * BSTR + bnc);
        cp16(db, srcB);
        cp16(db + 16, srcB + 4);
    };

    const int T = 8;
#pragma unroll
    for (int s = 0; s < 3; s++) { issue(s, s * 16); cp_commit(); }

    for (int i = 0; i < T; i++) {
        cp_wait2();
        __syncthreads();
        if (i + 3 < T) issue((i + 3) & 3, (i + 3) * 16);
        cp_commit();

        const unsigned* Ab = As + (i & 3) * A_WORDS;
        const unsigned* Bb = Bs + (i & 3) * B_WORDS;
#pragma unroll
        for (int kk = 0; kk < 16; kk += 8) {
            unsigned afr[4][4];
#pragma unroll
            for (int mt = 0; mt < 4; mt++) {
                int mr = m0 + mt * 16 + g;
                afr[mt][0] = Ab[mr * ASTR + kk + t];
                afr[mt][1] = Ab[(mr + 8) * ASTR + kk + t];
                afr[mt][2] = Ab[mr * ASTR + kk + t + 4];
                afr[mt][3] = Ab[(mr + 8) * ASTR + kk + t + 4];
            }
            unsigned bfr[4][2];
#pragma unroll
            for (int nt = 0; nt < 4; nt++) {
                int nr = n0 + nt * 8 + g;
                bfr[nt][0] = Bb[(kk + t) * BSTR + nr];
                bfr[nt][1] = Bb[(kk + t + 4) * BSTR + nr];
            }
#pragma unroll
            for (int mt = 0; mt < 4; mt++)
#pragma unroll
                for (int nt = 0; nt < 4; nt++)
                    mma_tf32(acc[mt][nt], afr[mt], bfr[nt]);
        }
    }

#pragma unroll
    for (int nt = 0; nt < 4; nt++) {
        int c = n0 + nt * 8 + 2 * t;
        if (c < 64) {
#pragma unroll
            for (int mt = 0; mt < 4; mt++) {
                int r0 = brow + m0 + mt * 16 + g;
                if (r0 < N_NODES)
                    *(float2*)(g_t + (size_t)r0 * 64 + c) =
                        make_float2(acc[mt][nt][0], acc[mt][nt][1]);
                int r1 = r0 + 8;
                if (r1 < N_NODES)
                    *(float2*)(g_t + (size_t)r1 * 64 + c) =
                        make_float2(acc[mt][nt][2], acc[mt][nt][3]);
            }
        } else {
            int co = c - 64;
            float2 bb = *(const float2*)(b2 + co);
#pragma unroll
            for (int mt = 0; mt < 4; mt++) {
                int r0 = brow + m0 + mt * 16 + g;
                if (r0 < N_NODES)
                    *(float2*)(out + (size_t)r0 * 64 + co) =
                        make_float2(acc[mt][nt][0] + bb.x, acc[mt][nt][1] + bb.y);
                int r1 = r0 + 8;
                if (r1 < N_NODES)
                    *(float2*)(out + (size_t)r1 * 64 + co) =
                        make_float2(acc[mt][nt][2] + bb.x, acc[mt][nt][3] + bb.y);
            }
        }
    }
}

// ---------------------------------------------------------------------------
// Aggregation 2 + final (unchanged)
// ---------------------------------------------------------------------------
__global__ void k_agg2(float* __restrict__ out) {
    int node = blockIdx.x * (blockDim.x >> 5) + (threadIdx.x >> 5);
    int lane = threadIdx.x & 31;
    if (node >= N_NODES) return;

    int deg = min(g_cnt[node], CAP);
    const int* adj = g_adj + node * CAP;

    float2 a0 = make_float2(0.f, 0.f);
    float2 a1 = make_float2(0.f, 0.f);
    float2 a2 = make_float2(0.f, 0.f);
    float2 a3 = make_float2(0.f, 0.f);

    int p = 0;
    for (; p + 8 <= deg; p += 8) {
        int4 i0 = *(const int4*)(adj + p);
        int4 i1 = *(const int4*)(adj + p + 4);
        float2 v0 = ((const float2*)(g_t + (size_t)i0.x * OUT_C))[lane];
        float2 v1 = ((const float2*)(g_t + (size_t)i0.y * OUT_C))[lane];
        float2 v2 = ((const float2*)(g_t + (size_t)i0.z * OUT_C))[lane];
        float2 v3 = ((const float2*)(g_t + (size_t)i0.w * OUT_C))[lane];
        float2 v4 = ((const float2*)(g_t + (size_t)i1.x * OUT_C))[lane];
        float2 v5 = ((const float2*)(g_t + (size_t)i1.y * OUT_C))[lane];
        float2 v6 = ((const float2*)(g_t + (size_t)i1.z * OUT_C))[lane];
        float2 v7 = ((const float2*)(g_t + (size_t)i1.w * OUT_C))[lane];
        a0.x += v0.x; a0.y += v0.y;
        a1.x += v1.x; a1.y += v1.y;
        a2.x += v2.x; a2.y += v2.y;
        a3.x += v3.x; a3.y += v3.y;
        a0.x += v4.x; a0.y += v4.y;
        a1.x += v5.x; a1.y += v5.y;
        a2.x += v6.x; a2.y += v6.y;
        a3.x += v7.x; a3.y += v7.y;
    }
    if (p + 4 <= deg) {
        int4 i0 = *(const int4*)(adj + p);
        float2 v0 = ((const float2*)(g_t + (size_t)i0.x * OUT_C))[lane];
        float2 v1 = ((const float2*)(g_t + (size_t)i0.y * OUT_C))[lane];
        float2 v2 = ((const float2*)(g_t + (size_t)i0.z * OUT_C))[lane];
        float2 v3 = ((const float2*)(g_t + (size_t)i0.w * OUT_C))[lane];
        a0.x += v0.x; a0.y += v0.y;
        a1.x += v1.x; a1.y += v1.y;
        a2.x += v2.x; a2.y += v2.y;
        a3.x += v3.x; a3.y += v3.y;
        p += 4;
    }
    for (; p < deg; p++) {
        int s = adj[p];
        float2 v = ((const float2*)(g_t + (size_t)s * OUT_C))[lane];
        a0.x += v.x; a0.y += v.y;
    }
    float inv = (deg > 0) ? 1.f / (float)deg : 0.f;
    float sx = ((a0.x + a1.x) + (a2.x + a3.x)) * inv;
    float sy = ((a0.y + a1.y) + (a2.y + a3.y)) * inv;

    float2* o = (float2*)(out + (size_t)node * OUT_C) + lane;
    float2 cur = *o;
    cur.x += sx;
    cur.y += sy;
    *o = cur;
}

// ---------------------------------------------------------------------------
extern "C" void kernel_launch(void* const* d_in, const int* in_sizes, int n_in,
                              void* d_out, int out_size) {
    const float* x   = (const float*)d_in[0];
    const int*   ei  = (const int*)d_in[1];     // int32 (JAX default x64 off)
    const float* W1l = (const float*)d_in[2];
    const float* b1  = (const float*)d_in[3];
    const float* W1r = (const float*)d_in[4];
    const float* W2l = (const float*)d_in[5];
    const float* b2  = (const float*)d_in[6];
    const float* W2r = (const float*)d_in[7];
    float* out = (float*)d_out;

    const int E = in_sizes[1] / 2;

    static bool attr_done = false;
    if (!attr_done) {
        cudaFuncSetAttribute(k_gemm1, cudaFuncAttributeMaxDynamicSharedMemorySize, DSMEM_BYTES);
        cudaFuncSetAttribute(k_gemm2, cudaFuncAttributeMaxDynamicSharedMemorySize, DSMEM_BYTES);
        attr_done = true;
    }

    k_cvt<<<1024, 256>>>(x, W1l, W1r, W2l, W2r);
    k_fill<<<(E + 255) / 256, 256>>>(ei, E);

    k_agg1<<<(N_NODES + 7) / 8, 256>>>(x);
    k_gemm1<<<(N_NODES + 127) / 128, 256, DSMEM_BYTES>>>(b1);

    k_gemm2<<<(N_NODES + 127) / 128, 256, DSMEM_BYTES>>>(b2, out);
    k_agg2<<<(N_NODES + 7) / 8, 256>>>(out);
}

// round 17
// speedup vs baseline: 1.7774x; 1.0722x over previous
#include <cuda_runtime.h>
#include <cuda_fp16.h>

#define N_NODES 50000
#define IN_C   128
#define HID_C  128
#define OUT_C  64
#define CAP    128          // neighbor bucket capacity (Poisson mean 16 -> safe)

// ---------------------------------------------------------------------------
// Device-global scratch (no allocations allowed)
// ---------------------------------------------------------------------------
__device__ int    g_cnt [N_NODES];
__device__ int    g_adj [N_NODES * CAP];
__device__ float  g_mean[N_NODES * IN_C];      // mean of neighbor x (tf32-rounded)
__device__ float  g_xt  [N_NODES * IN_C];      // x, tf32-rounded (GEMM operand)
__device__ __half g_xh  [N_NODES * IN_C];      // x, fp16 (gather operand)
__device__ float  g_w1  [256 * 128];           // [W1_l ; W1_r], tf32-rounded
__device__ float  g_w2  [128 * 128];           // [W2_l | W2_r], tf32-rounded
__device__ float  g_h   [N_NODES * HID_C];     // layer-1 activations (tf32-rounded)
__device__ __half g_th  [N_NODES * OUT_C];     // h @ W2_l, fp16 (gather operand)

// ---------------------------------------------------------------------------
__device__ __forceinline__ unsigned f2tf32(float f) {
    unsigned u;
    asm("cvt.rna.tf32.f32 %0, %1;" : "=r"(u) : "f"(f));
    return u;
}
__device__ __forceinline__ float rnd32(float f) { return __uint_as_float(f2tf32(f)); }

__device__ __forceinline__ float4 h4tof4(uint2 u) {
    __half2 h0 = *reinterpret_cast<__half2*>(&u.x);
    __half2 h1 = *reinterpret_cast<__half2*>(&u.y);
    float2 f0 = __half22float2(h0);
    float2 f1 = __half22float2(h1);
    return make_float4(f0.x, f0.y, f1.x, f1.y);
}

// ---------------------------------------------------------------------------
// k_cvt: pre-round x (tf32 + fp16) and weights (tf32); zeroes g_cnt.
// ---------------------------------------------------------------------------
__global__ void k_cvt(const float* __restrict__ x,
                      const float* __restrict__ W1l, const float* __restrict__ W1r,
                      const float* __restrict__ W2l, const float* __restrict__ W2r) {
    const int NX4  = N_NODES * IN_C / 4;
    const int NW14 = 256 * 128 / 4;
    const int NW24 = 128 * 128 / 4;
    const int total = NX4 + NW14 + NW24;
    const int stride = gridDim.x * blockDim.x;
    for (int i = blockIdx.x * blockDim.x + threadIdx.x; i < total; i += stride) {
        if (i < NX4) {
            float4 v = ((const float4*)x)[i];
            float4 o;
            o.x = rnd32(v.x); o.y = rnd32(v.y); o.z = rnd32(v.z); o.w = rnd32(v.w);
            ((float4*)g_xt)[i] = o;
            uint2 h;
            *reinterpret_cast<__half2*>(&h.x) = __floats2half2_rn(v.x, v.y);
            *reinterpret_cast<__half2*>(&h.y) = __floats2half2_rn(v.z, v.w);
            ((uint2*)g_xh)[i] = h;
        } else if (i < NX4 + NW14) {
            int j = i - NX4;
            int e = j * 4, r = e >> 7, c = e & 127;
            const float* s = (r < 128) ? (W1l + r * 128 + c) : (W1r + (r - 128) * 128 + c);
            float4 v = *(const float4*)s;
            float4 o;
            o.x = rnd32(v.x); o.y = rnd32(v.y); o.z = rnd32(v.z); o.w = rnd32(v.w);
            ((float4*)g_w1)[j] = o;
        } else {
            int j = i - NX4 - NW14;
            int e = j * 4, r = e >> 7, c = e & 127;
            const float* s = (c < 64) ? (W2l + r * 64 + c) : (W2r + r * 64 + (c - 64));
            float4 v = *(const float4*)s;
            float4 o;
            o.x = rnd32(v.x); o.y = rnd32(v.y); o.z = rnd32(v.z); o.w = rnd32(v.w);
            ((float4*)g_w2)[j] = o;
        }
    }
    for (int i = blockIdx.x * blockDim.x + threadIdx.x; i < N_NODES; i += stride)
        g_cnt[i] = 0;
}

// ---------------------------------------------------------------------------
__global__ void k_fill(const int* __restrict__ ei, int E) {
    int e = blockIdx.x * blockDim.x + threadIdx.x;
    if (e >= E) return;
    int s = ei[e];
    int d = ei[E + e];
    int pos = atomicAdd(&g_cnt[d], 1);
    if (pos < CAP) g_adj[d * CAP + pos] = s;
}

// ---------------------------------------------------------------------------
// Aggregation 1 (fp16 gather, fp32 accumulate): one warp per node.
// Lane owns channels 4*lane..4*lane+3 (uint2 = 4 halves = 8B; 256B/warp row).
// ---------------------------------------------------------------------------
__global__ void k_agg1() {
    int node = blockIdx.x * (blockDim.x >> 5) + (threadIdx.x >> 5);
    int lane = threadIdx.x & 31;
    if (node >= N_NODES) return;

    int deg = min(g_cnt[node], CAP);
    const int* adj = g_adj + node * CAP;

    float4 a0 = make_float4(0.f, 0.f, 0.f, 0.f);
    float4 a1 = make_float4(0.f, 0.f, 0.f, 0.f);
    float4 a2 = make_float4(0.f, 0.f, 0.f, 0.f);
    float4 a3 = make_float4(0.f, 0.f, 0.f, 0.f);

    int p = 0;
    for (; p + 8 <= deg; p += 8) {
        int4 i0 = *(const int4*)(adj + p);
        int4 i1 = *(const int4*)(adj + p + 4);
        float4 v0 = h4tof4(((const uint2*)(g_xh + (size_t)i0.x * IN_C))[lane]);
        float4 v1 = h4tof4(((const uint2*)(g_xh + (size_t)i0.y * IN_C))[lane]);
        float4 v2 = h4tof4(((const uint2*)(g_xh + (size_t)i0.z * IN_C))[lane]);
        float4 v3 = h4tof4(((const uint2*)(g_xh + (size_t)i0.w * IN_C))[lane]);
        float4 v4 = h4tof4(((const uint2*)(g_xh + (size_t)i1.x * IN_C))[lane]);
        float4 v5 = h4tof4(((const uint2*)(g_xh + (size_t)i1.y * IN_C))[lane]);
        float4 v6 = h4tof4(((const uint2*)(g_xh + (size_t)i1.z * IN_C))[lane]);
        float4 v7 = h4tof4(((const uint2*)(g_xh + (size_t)i1.w * IN_C))[lane]);
        a0.x += v0.x; a0.y += v0.y; a0.z += v0.z; a0.w += v0.w;
        a1.x += v1.x; a1.y += v1.y; a1.z += v1.z; a1.w += v1.w;
        a2.x += v2.x; a2.y += v2.y; a2.z += v2.z; a2.w += v2.w;
        a3.x += v3.x; a3.y += v3.y; a3.z += v3.z; a3.w += v3.w;
        a0.x += v4.x; a0.y += v4.y; a0.z += v4.z; a0.w += v4.w;
        a1.x += v5.x; a1.y += v5.y; a1.z += v5.z; a1.w += v5.w;
        a2.x += v6.x; a2.y += v6.y; a2.z += v6.z; a2.w += v6.w;
        a3.x += v7.x; a3.y += v7.y; a3.z += v7.z; a3.w += v7.w;
    }
    if (p + 4 <= deg) {
        int4 i0 = *(const int4*)(adj + p);
        float4 v0 = h4tof4(((const uint2*)(g_xh + (size_t)i0.x * IN_C))[lane]);
        float4 v1 = h4tof4(((const uint2*)(g_xh + (size_t)i0.y * IN_C))[lane]);
        float4 v2 = h4tof4(((const uint2*)(g_xh + (size_t)i0.z * IN_C))[lane]);
        float4 v3 = h4tof4(((const uint2*)(g_xh + (size_t)i0.w * IN_C))[lane]);
        a0.x += v0.x; a0.y += v0.y; a0.z += v0.z; a0.w += v0.w;
        a1.x += v1.x; a1.y += v1.y; a1.z += v1.z; a1.w += v1.w;
        a2.x += v2.x; a2.y += v2.y; a2.z += v2.z; a2.w += v2.w;
        a3.x += v3.x; a3.y += v3.y; a3.z += v3.z; a3.w += v3.w;
        p += 4;
    }
    for (; p < deg; p++) {
        int s = adj[p];
        float4 v = h4tof4(((const uint2*)(g_xh + (size_t)s * IN_C))[lane]);
        a0.x += v.x; a0.y += v.y; a0.z += v.z; a0.w += v.w;
    }
    float4 acc;
    acc.x = (a0.x + a1.x) + (a2.x + a3.x);
    acc.y = (a0.y + a1.y) + (a2.y + a3.y);
    acc.z = (a0.z + a1.z) + (a2.z + a3.z);
    acc.w = (a0.w + a1.w) + (a2.w + a3.w);
    float inv = (deg > 0) ? 1.f / (float)deg : 0.f;
    acc.x = rnd32(acc.x * inv);
    acc.y = rnd32(acc.y * inv);
    acc.z = rnd32(acc.z * inv);
    acc.w = rnd32(acc.w * inv);
    ((float4*)(g_mean + (size_t)node * IN_C))[lane] = acc;
}

// ---------------------------------------------------------------------------
// MMA + cp.async helpers
// ---------------------------------------------------------------------------
__device__ __forceinline__ void mma_tf32(float d[4], const unsigned a[4],
                                         const unsigned b[2]) {
    asm volatile(
        "mma.sync.aligned.m16n8k8.row.col.f32.tf32.tf32.f32 "
        "{%0,%1,%2,%3}, {%4,%5,%6,%7}, {%8,%9}, {%0,%1,%2,%3};"
        : "+f"(d[0]), "+f"(d[1]), "+f"(d[2]), "+f"(d[3])
        : "r"(a[0]), "r"(a[1]), "r"(a[2]), "r"(a[3]), "r"(b[0]), "r"(b[1]));
}
__device__ __forceinline__ unsigned sptr(const void* p) {
    return (unsigned)__cvta_generic_to_shared(p);
}
__device__ __forceinline__ void cp16(unsigned d, const void* s) {
    asm volatile("cp.async.cg.shared.global [%0], [%1], 16;" :: "r"(d), "l"(s) : "memory");
}
__device__ __forceinline__ void cp_commit() {
    asm volatile("cp.async.commit_group;" ::: "memory");
}
__device__ __forceinline__ void cp_wait2() {
    asm volatile("cp.async.wait_group 2;" ::: "memory");
}

#define ASTR 20
#define BSTR 136
#define NSTAGE 4
#define A_WORDS (128 * ASTR)
#define B_WORDS (16 * BSTR)
#define DSMEM_BYTES (NSTAGE * (A_WORDS + B_WORDS) * 4)

extern __shared__ unsigned dyn_smem[];

// ---------------------------------------------------------------------------
// GEMM 1 (TF32, 4-stage cp.async): h = relu( [mean | x] @ g_w1 + b1 )  K=256
// ---------------------------------------------------------------------------
__global__ __launch_bounds__(256) void k_gemm1(const float* __restrict__ b1) {
    unsigned* As = dyn_smem;
    unsigned* Bs = dyn_smem + NSTAGE * A_WORDS;

    const int tid  = threadIdx.x;
    const int brow = blockIdx.x * 128;

    const int am  = tid & 127;
    const int akb = (tid >> 7) * 8;
    const int ra  = min(brow + am, N_NODES - 1);
    const int bkr = tid >> 4;
    const int bnc = (tid & 15) * 8;

    const int wid  = tid >> 5;
    const int lane = tid & 31;
    const int g    = lane >> 2;
    const int t    = lane & 3;
    const int m0   = (wid >> 2) * 64;
    const int n0   = (wid & 3) * 32;

    float acc[4][4][4];
#pragma unroll
    for (int mt = 0; mt < 4; mt++)
#pragma unroll
        for (int nt = 0; nt < 4; nt++)
#pragma unroll
            for (int r = 0; r < 4; r++) acc[mt][nt][r] = 0.f;

    auto issue = [&](int st, int kc) {
        int kg = kc + akb;
        const float* srcA = (kg < 128) ? (g_mean + (size_t)ra * 128 + kg)
                                       : (g_xt + (size_t)ra * 128 + (kg - 128));
        unsigned da = sptr(As + st * A_WORDS + am * ASTR + akb);
        cp16(da, srcA);
        cp16(da + 16, srcA + 4);
        const float* srcB = g_w1 + (size_t)(kc + bkr) * 128 + bnc;
        unsigned db = sptr(Bs + st * B_WORDS + bkr * BSTR + bnc);
        cp16(db, srcB);
        cp16(db + 16, srcB + 4);
    };

    const int T = 16;
#pragma unroll
    for (int s = 0; s < 3; s++) { issue(s, s * 16); cp_commit(); }

    for (int i = 0; i < T; i++) {
        cp_wait2();
        __syncthreads();
        if (i + 3 < T) issue((i + 3) & 3, (i + 3) * 16);
        cp_commit();

        const unsigned* Ab = As + (i & 3) * A_WORDS;
        const unsigned* Bb = Bs + (i & 3) * B_WORDS;
#pragma unroll
        for (int kk = 0; kk < 16; kk += 8) {
            unsigned afr[4][4];
#pragma unroll
            for (int mt = 0; mt < 4; mt++) {
                int mr = m0 + mt * 16 + g;
                afr[mt][0] = Ab[mr * ASTR + kk + t];
                afr[mt][1] = Ab[(mr + 8) * ASTR + kk + t];
                afr[mt][2] = Ab[mr * ASTR + kk + t + 4];
                afr[mt][3] = Ab[(mr + 8) * ASTR + kk + t + 4];
            }
            unsigned bfr[4][2];
#pragma unroll
            for (int nt = 0; nt < 4; nt++) {
                int nr = n0 + nt * 8 + g;
                bfr[nt][0] = Bb[(kk + t) * BSTR + nr];
                bfr[nt][1] = Bb[(kk + t + 4) * BSTR + nr];
            }
#pragma unroll
            for (int mt = 0; mt < 4; mt++)
#pragma unroll
                for (int nt = 0; nt < 4; nt++)
                    mma_tf32(acc[mt][nt], afr[mt], bfr[nt]);
        }
    }

#pragma unroll
    for (int nt = 0; nt < 4; nt++) {
        int c = n0 + nt * 8 + 2 * t;
        float2 bb = *(const float2*)(b1 + c);
#pragma unroll
        for (int mt = 0; mt < 4; mt++) {
            int r0 = brow + m0 + mt * 16 + g;
            if (r0 < N_NODES) {
                float2 o;
                o.x = rnd32(fmaxf(acc[mt][nt][0] + bb.x, 0.f));
                o.y = rnd32(fmaxf(acc[mt][nt][1] + bb.y, 0.f));
                *(float2*)(g_h + (size_t)r0 * 128 + c) = o;
            }
            int r1 = r0 + 8;
            if (r1 < N_NODES) {
                float2 o;
                o.x = rnd32(fmaxf(acc[mt][nt][2] + bb.x, 0.f));
                o.y = rnd32(fmaxf(acc[mt][nt][3] + bb.y, 0.f));
                *(float2*)(g_h + (size_t)r1 * 128 + c) = o;
            }
        }
    }
}

// ---------------------------------------------------------------------------
// GEMM 2 (TF32, 4-stage cp.async): t(fp16) = h @ W2_l ; out = h @ W2_r + b2
// ---------------------------------------------------------------------------
__global__ __launch_bounds__(256) void k_gemm2(const float* __restrict__ b2,
                                               float* __restrict__ out) {
    unsigned* As = dyn_smem;
    unsigned* Bs = dyn_smem + NSTAGE * A_WORDS;

    const int tid  = threadIdx.x;
    const int brow = blockIdx.x * 128;

    const int am  = tid & 127;
    const int akb = (tid >> 7) * 8;
    const int ra  = min(brow + am, N_NODES - 1);
    const int bkr = tid >> 4;
    const int bnc = (tid & 15) * 8;

    const int wid  = tid >> 5;
    const int lane = tid & 31;
    const int g    = lane >> 2;
    const int t    = lane & 3;
    const int m0   = (wid >> 2) * 64;
    const int n0   = (wid & 3) * 32;

    float acc[4][4][4];
#pragma unroll
    for (int mt = 0; mt < 4; mt++)
#pragma unroll
        for (int nt = 0; nt < 4; nt++)
#pragma unroll
            for (int r = 0; r < 4; r++) acc[mt][nt][r] = 0.f;

    auto issue = [&](int st, int kc) {
        const float* srcA = g_h + (size_t)ra * 128 + kc + akb;
        unsigned da = sptr(As + st * A_WORDS + am * ASTR + akb);
        cp16(da, srcA);
        cp16(da + 16, srcA + 4);
        const float* srcB = g_w2 + (size_t)(kc + bkr) * 128 + bnc;
        unsigned db = sptr(Bs + st * B_WORDS + bkr * BSTR + bnc);
        cp16(db, srcB);
        cp16(db + 16, srcB + 4);
    };

    const int T = 8;
#pragma unroll
    for (int s = 0; s < 3; s++) { issue(s, s * 16); cp_commit(); }

    for (int i = 0; i < T; i++) {
        cp_wait2();
        __syncthreads();
        if (i + 3 < T) issue((i + 3) & 3, (i + 3) * 16);
        cp_commit();

        const unsigned* Ab = As + (i & 3) * A_WORDS;
        const unsigned* Bb = Bs + (i & 3) * B_WORDS;
#pragma unroll
        for (int kk = 0; kk < 16; kk += 8) {
            unsigned afr[4][4];
#pragma unroll
            for (int mt = 0; mt < 4; mt++) {
                int mr = m0 + mt * 16 + g;
                afr[mt][0] = Ab[mr * ASTR + kk + t];
                afr[mt][1] = Ab[(mr + 8) * ASTR + kk + t];
                afr[mt][2] = Ab[mr * ASTR + kk + t + 4];
                afr[mt][3] = Ab[(mr + 8) * ASTR + kk + t + 4];
            }
            unsigned bfr[4][2];
#pragma unroll
            for (int nt = 0; nt < 4; nt++) {
                int nr = n0 + nt * 8 + g;
                bfr[nt][0] = Bb[(kk + t) * BSTR + nr];
                bfr[nt][1] = Bb[(kk + t + 4) * BSTR + nr];
            }
#pragma unroll
            for (int mt = 0; mt < 4; mt++)
#pragma unroll
                for (int nt = 0; nt < 4; nt++)
                    mma_tf32(acc[mt][nt], afr[mt], bfr[nt]);
        }
    }

#pragma unroll
    for (int nt = 0; nt < 4; nt++) {
        int c = n0 + nt * 8 + 2 * t;
        if (c < 64) {
            // t = h @ W2_l -> fp16 gather operand
#pragma unroll
            for (int mt = 0; mt < 4; mt++) {
                int r0 = brow + m0 + mt * 16 + g;
                if (r0 < N_NODES)
                    *(__half2*)(g_th + (size_t)r0 * 64 + c) =
                        __floats2half2_rn(acc[mt][nt][0], acc[mt][nt][1]);
                int r1 = r0 + 8;
                if (r1 < N_NODES)
                    *(__half2*)(g_th + (size_t)r1 * 64 + c) =
                        __floats2half2_rn(acc[mt][nt][2], acc[mt][nt][3]);
            }
        } else {
            int co = c - 64;
            float2 bb = *(const float2*)(b2 + co);
#pragma unroll
            for (int mt = 0; mt < 4; mt++) {
                int r0 = brow + m0 + mt * 16 + g;
                if (r0 < N_NODES)
                    *(float2*)(out + (size_t)r0 * 64 + co) =
                        make_float2(acc[mt][nt][0] + bb.x, acc[mt][nt][1] + bb.y);
                int r1 = r0 + 8;
                if (r1 < N_NODES)
                    *(float2*)(out + (size_t)r1 * 64 + co) =
                        make_float2(acc[mt][nt][2] + bb.x, acc[mt][nt][3] + bb.y);
            }
        }
    }
}

// ---------------------------------------------------------------------------
// Aggregation 2 + final (fp16 gather): out[n] += mean_{s in N(n)} t[s]
// Lane owns channels 2*lane, 2*lane+1 (half2 = 4B; 128B/warp row).
// ---------------------------------------------------------------------------
__global__ void k_agg2(float* __restrict__ out) {
    int node = blockIdx.x * (blockDim.x >> 5) + (threadIdx.x >> 5);
    int lane = threadIdx.x & 31;
    if (node >= N_NODES) return;

    int deg = min(g_cnt[node], CAP);
    const int* adj = g_adj + node * CAP;

    float2 a0 = make_float2(0.f, 0.f);
    float2 a1 = make_float2(0.f, 0.f);
    float2 a2 = make_float2(0.f, 0.f);
    float2 a3 = make_float2(0.f, 0.f);

    int p = 0;
    for (; p + 8 <= deg; p += 8) {
        int4 i0 = *(const int4*)(adj + p);
        int4 i1 = *(const int4*)(adj + p + 4);
        float2 v0 = __half22float2(((const __half2*)(g_th + (size_t)i0.x * OUT_C))[lane]);
        float2 v1 = __half22float2(((const __half2*)(g_th + (size_t)i0.y * OUT_C))[lane]);
        float2 v2 = __half22float2(((const __half2*)(g_th + (size_t)i0.z * OUT_C))[lane]);
        float2 v3 = __half22float2(((const __half2*)(g_th + (size_t)i0.w * OUT_C))[lane]);
        float2 v4 = __half22float2(((const __half2*)(g_th + (size_t)i1.x * OUT_C))[lane]);
        float2 v5 = __half22float2(((const __half2*)(g_th + (size_t)i1.y * OUT_C))[lane]);
        float2 v6 = __half22float2(((const __half2*)(g_th + (size_t)i1.z * OUT_C))[lane]);
        float2 v7 = __half22float2(((const __half2*)(g_th + (size_t)i1.w * OUT_C))[lane]);
        a0.x += v0.x; a0.y += v0.y;
        a1.x += v1.x; a1.y += v1.y;
        a2.x += v2.x; a2.y += v2.y;
        a3.x += v3.x; a3.y += v3.y;
        a0.x += v4.x; a0.y += v4.y;
        a1.x += v5.x; a1.y += v5.y;
        a2.x += v6.x; a2.y += v6.y;
        a3.x += v7.x; a3.y += v7.y;
    }
    if (p + 4 <= deg) {
        int4 i0 = *(const int4*)(adj + p);
        float2 v0 = __half22float2(((const __half2*)(g_th + (size_t)i0.x * OUT_C))[lane]);
        float2 v1 = __half22float2(((const __half2*)(g_th + (size_t)i0.y * OUT_C))[lane]);
        float2 v2 = __half22float2(((const __half2*)(g_th + (size_t)i0.z * OUT_C))[lane]);
        float2 v3 = __half22float2(((const __half2*)(g_th + (size_t)i0.w * OUT_C))[lane]);
        a0.x += v0.x; a0.y += v0.y;
        a1.x += v1.x; a1.y += v1.y;
        a2.x += v2.x; a2.y += v2.y;
        a3.x += v3.x; a3.y += v3.y;
        p += 4;
    }
    for (; p < deg; p++) {
        int s = adj[p];
        float2 v = __half22float2(((const __half2*)(g_th + (size_t)s * OUT_C))[lane]);
        a0.x += v.x; a0.y += v.y;
    }
    float inv = (deg > 0) ? 1.f / (float)deg : 0.f;
    float sx = ((a0.x + a1.x) + (a2.x + a3.x)) * inv;
    float sy = ((a0.y + a1.y) + (a2.y + a3.y)) * inv;

    float2* o = (float2*)(out + (size_t)node * OUT_C) + lane;
    float2 cur = *o;
    cur.x += sx;
    cur.y += sy;
    *o = cur;
}

// ---------------------------------------------------------------------------
extern "C" void kernel_launch(void* const* d_in, const int* in_sizes, int n_in,
                              void* d_out, int out_size) {
    const float* x   = (const float*)d_in[0];
    const int*   ei  = (const int*)d_in[1];     // int32 (JAX default x64 off)
    const float* W1l = (const float*)d_in[2];
    const float* b1  = (const float*)d_in[3];
    const float* W1r = (const float*)d_in[4];
    const float* W2l = (const float*)d_in[5];
    const float* b2  = (const float*)d_in[6];
    const float* W2r = (const float*)d_in[7];
    float* out = (float*)d_out;

    const int E = in_sizes[1] / 2;

    static bool attr_done = false;
    if (!attr_done) {
        cudaFuncSetAttribute(k_gemm1, cudaFuncAttributeMaxDynamicSharedMemorySize, DSMEM_BYTES);
        cudaFuncSetAttribute(k_gemm2, cudaFuncAttributeMaxDynamicSharedMemorySize, DSMEM_BYTES);
        attr_done = true;
    }

    k_cvt<<<1024, 256>>>(x, W1l, W1r, W2l, W2r);
    k_fill<<<(E + 255) / 256, 256>>>(ei, E);

    k_agg1<<<(N_NODES + 7) / 8, 256>>>();
    k_gemm1<<<(N_NODES + 127) / 128, 256, DSMEM_BYTES>>>(b1);

    k_gemm2<<<(N_NODES + 127) / 128, 256, DSMEM_BYTES>>>(b2, out);
    k_agg2<<<(N_NODES + 7) / 8, 256>>>(out);
}